// round 10
// baseline (speedup 1.0000x reference)
#include <cuda_runtime.h>
#include <math.h>
#include <stdint.h>

#define Bsz  4096
#define Din  512
#define Hd   1024
#define KE   8
#define Oo   256
#define NHh  4
#define HDim 256
#define EPSv 1e-5f

// ---------------- scratch (device globals; no allocations allowed) ----------
__device__ float g_gi[(size_t)Bsz * KE * 3 * Hd];   // (B, K, 3H)
__device__ float g_gh[(size_t)Bsz * KE * 3 * Hd];   // (B, K, 3H)
__device__ float g_query[(size_t)Bsz * Hd];
__device__ float g_q[(size_t)Bsz * Hd];
__device__ float g_kmat[(size_t)Bsz * KE * Hd];
__device__ float g_vmat[(size_t)Bsz * KE * Hd];
__device__ float g_ctx[(size_t)Bsz * Hd];
__device__ float g_attnout[(size_t)Bsz * Hd];
__device__ float g_context[(size_t)Bsz * Hd];
__device__ float g_mixed[(size_t)Bsz * Hd];

// tf32-rounded operand copies (bit-identical to what R9's in-loop cvt produced)
__device__ float g_xr[(size_t)Bsz * Din];
__device__ float g_hpr[(size_t)Bsz * KE * Hd];
__device__ float g_Wihr[(size_t)KE * 3 * Hd * Din];
__device__ float g_Whhr[(size_t)KE * 3 * Hd * Hd];
__device__ float g_Wqpr[(size_t)Hd * Din];
__device__ float g_Wqr[(size_t)Hd * Hd];
__device__ float g_Wkr[(size_t)Hd * Hd];
__device__ float g_Wvr[(size_t)Hd * Hd];
__device__ float g_Wor[(size_t)Hd * Hd];
__device__ float g_Wrdr[(size_t)Oo * Hd];
__device__ float g_queryr[(size_t)Bsz * Hd];
__device__ float g_hnewr[(size_t)Bsz * KE * Hd];
__device__ float g_ctxr[(size_t)Bsz * Hd];
__device__ float g_mixedr[(size_t)Bsz * Hd];

// ---------------- helpers ----------------------------------------------------
__device__ __forceinline__ float to_tf32(float x) {
    float r; asm("cvt.rna.tf32.f32 %0, %1;" : "=f"(r) : "f"(x)); return r;
}
__device__ __forceinline__ void mma16n8k8(float* c, const uint32_t* a, const uint32_t* b) {
    asm volatile("mma.sync.aligned.m16n8k8.row.col.f32.tf32.tf32.f32 "
        "{%0,%1,%2,%3}, {%4,%5,%6,%7}, {%8,%9}, {%0,%1,%2,%3};"
        : "+f"(c[0]), "+f"(c[1]), "+f"(c[2]), "+f"(c[3])
        : "r"(a[0]), "r"(a[1]), "r"(a[2]), "r"(a[3]), "r"(b[0]), "r"(b[1]));
}
__device__ __forceinline__ uint32_t smem_u32(const void* p) {
    uint32_t a;
    asm("{ .reg .u64 t; cvta.to.shared.u64 t, %1; cvt.u32.u64 %0, t; }" : "=r"(a) : "l"(p));
    return a;
}
__device__ __forceinline__ void cp_async16(uint32_t dst, const void* src) {
    asm volatile("cp.async.cg.shared.global [%0], [%1], 16;" :: "r"(dst), "l"(src));
}
#define CP_COMMIT()  asm volatile("cp.async.commit_group;" ::: "memory")
#define CP_WAIT(n)   asm volatile("cp.async.wait_group %0;" :: "n"(n) : "memory")

// ---------------- elementwise tf32 rounding ----------------------------------
__global__ void round_tf32_kernel(const float4* __restrict__ in, float4* __restrict__ out, int n4)
{
    int i = blockIdx.x * 256 + threadIdx.x;
    if (i < n4) {
        float4 v = in[i];
        v.x = to_tf32(v.x); v.y = to_tf32(v.y); v.z = to_tf32(v.z); v.w = to_tf32(v.w);
        out[i] = v;
    }
}

// ================= tf32 mma.sync TN GEMM (pre-rounded operands) ==============
// C[m,n] = sum_k A[m,k]*B[n,k] + bias[n]; A,B already tf32-valued fp32.
// CTA tile 256(M) x 128(N), K-chunk 32, 256 threads.
// 8 warps = 4(M) x 2(N), warp tile 64x64 (acc 128 regs).
// 3-stage cp.async, ONE barrier per chunk, uniform group-count invariant
// (empty commit in tail) so wait_group(1) always retires chunk c's group.
#define STG_AW  (256 * 36)                   // A stage words
#define STG_BW  (128 * 36)                   // B stage words
#define STAGE_W (STG_AW + STG_BW)            // 13824 words
#define NSTAGE  3
#define SMEMB   (NSTAGE * STAGE_W * 4)       // 165888 bytes

__global__ __launch_bounds__(256, 1)
void mma_tn(const float* __restrict__ A, const float* __restrict__ Bm,
            const float* __restrict__ bias, float* __restrict__ C,
            float* __restrict__ Cr,          // optional tf32-rounded copy of C
            int Kd, int lda, int ldb, int ldc,
            long aBat, long bBat, long cBat, long biasBat)
{
    extern __shared__ float smf[];
    const int tid  = threadIdx.x;
    const int wid  = tid >> 5;
    const int lane = tid & 31;
    const int warpM = wid & 3;        // 0..3  (64 rows each)
    const int warpN = wid >> 2;       // 0..1  (64 cols each)
    const int r = lane >> 2;          // 0..7
    const int q = lane & 3;           // 0..3

    const int bz = blockIdx.z;
    A  += (long)bz * aBat;
    Bm += (long)bz * bBat;
    C  += (long)bz * cBat;
    const float* biasp = bias ? bias + (long)bz * biasBat : nullptr;

    const int rowBase = blockIdx.y * 256;
    const int colBase = blockIdx.x * 128;

    const int lrow = tid >> 3;        // 0..31
    const int lc4  = (tid & 7) * 4;   // 0,4,...,28

    const uint32_t smb = smem_u32(smf);

    // one 32-wide K chunk into stage s (A: 256 rows, B: 128 rows) = one group
    auto issue_chunk = [&](int k0, int s) {
        const uint32_t abase = smb + (s * STAGE_W) * 4;
        const uint32_t bbase = abase + STG_AW * 4;
        const uint32_t soff = (lrow * 36 + lc4) * 4;
        #pragma unroll
        for (int i = 0; i < 8; i++) {
            int row = lrow + i * 32;
            cp_async16(abase + soff + i * (32 * 36 * 4),
                       A + (long)(rowBase + row) * lda + k0 + lc4);
        }
        #pragma unroll
        for (int i = 0; i < 4; i++) {
            int row = lrow + i * 32;
            cp_async16(bbase + soff + i * (32 * 36 * 4),
                       Bm + (long)(colBase + row) * ldb + k0 + lc4);
        }
        CP_COMMIT();
    };

    float acc[4][8][4];
    #pragma unroll
    for (int mt = 0; mt < 4; mt++)
        #pragma unroll
        for (int nt = 0; nt < 8; nt++)
            #pragma unroll
            for (int j = 0; j < 4; j++) acc[mt][nt][j] = 0.0f;

    const int NC = Kd >> 5;

    issue_chunk(0, 0);                       // G0
    if (NC > 1) issue_chunk(32, 1);          // G1
    else        CP_COMMIT();

    for (int c = 0; c < NC; c++) {
        CP_WAIT(1);                // newest group is G(c+1) -> G(c) retired
        __syncthreads();           // all warps done reading stage (c-1)%3

        if (c + 2 < NC) issue_chunk((c + 2) * 32, (c + 2) % NSTAGE);
        else            CP_COMMIT();        // keep group numbering uniform

        const int s = c % NSTAGE;
        const float* as = smf + s * STAGE_W + (warpM * 64) * 36;
        const float* bs = smf + s * STAGE_W + STG_AW + (warpN * 64) * 36;

        #pragma unroll
        for (int ks = 0; ks < 4; ks++) {
            const int k0 = ks * 8;
            uint32_t afr[4][4];
            #pragma unroll
            for (int mt = 0; mt < 4; mt++) {
                const float* ap = as + (mt * 16 + r) * 36 + k0 + q;
                afr[mt][0] = __float_as_uint(ap[0]);
                afr[mt][1] = __float_as_uint(ap[8 * 36]);
                afr[mt][2] = __float_as_uint(ap[4]);
                afr[mt][3] = __float_as_uint(ap[8 * 36 + 4]);
            }
            #pragma unroll
            for (int nt = 0; nt < 8; nt++) {
                const float* bp = bs + (nt * 8 + r) * 36 + k0 + q;
                uint32_t bfr[2];
                bfr[0] = __float_as_uint(bp[0]);
                bfr[1] = __float_as_uint(bp[4]);
                #pragma unroll
                for (int mt = 0; mt < 4; mt++)
                    mma16n8k8(acc[mt][nt], afr[mt], bfr);
            }
        }
    }

    // ---- epilogue: acc -> C (+bias), optional rounded copy ----
    #pragma unroll
    for (int mt = 0; mt < 4; mt++) {
        const int row = rowBase + warpM * 64 + mt * 16 + r;
        #pragma unroll
        for (int nt = 0; nt < 8; nt++) {
            const int col = colBase + warpN * 64 + nt * 8 + q * 2;
            float b0 = 0.f, b1 = 0.f;
            if (biasp) { b0 = biasp[col]; b1 = biasp[col + 1]; }
            float2 v0, v1;
            v0.x = acc[mt][nt][0] + b0; v0.y = acc[mt][nt][1] + b1;
            v1.x = acc[mt][nt][2] + b0; v1.y = acc[mt][nt][3] + b1;
            *(float2*)(C + (long)row * ldc + col)       = v0;
            *(float2*)(C + (long)(row + 8) * ldc + col) = v1;
            if (Cr) {
                float2 r0, r1;
                r0.x = to_tf32(v0.x); r0.y = to_tf32(v0.y);
                r1.x = to_tf32(v1.x); r1.y = to_tf32(v1.y);
                *(float2*)(Cr + (long)row * ldc + col)       = r0;
                *(float2*)(Cr + (long)(row + 8) * ldc + col) = r1;
            }
        }
    }
}

// ---------------- GRU pointwise + per-expert LayerNorm -----------------------
__global__ void gru_ln_kernel(const float* __restrict__ gi, const float* __restrict__ gh,
                              const float* __restrict__ h_prev,
                              const float* __restrict__ ln_g, const float* __restrict__ ln_b,
                              float* __restrict__ h_new, float* __restrict__ h_new_r)
{
    const int bk = blockIdx.x;
    const int k  = bk & (KE - 1);
    const long giBase = (long)bk * (3 * Hd);
    const long hBase  = (long)bk * Hd;
    const float* gir = gi + giBase;
    const float* ghr = gh + giBase;
    const float* hp  = h_prev + hBase;

    float vals[4];
    float s = 0.f, ss = 0.f;
    #pragma unroll
    for (int t = 0; t < 4; t++) {
        int h = threadIdx.x + t * 256;
        float ir = gir[h],           hr = ghr[h];
        float iz = gir[Hd + h],      hz = ghr[Hd + h];
        float inn = gir[2 * Hd + h], hn = ghr[2 * Hd + h];
        float r = 1.f / (1.f + expf(-(ir + hr)));
        float z = 1.f / (1.f + expf(-(iz + hz)));
        float n = tanhf(inn + r * hn);
        float hv = (1.f - z) * n + z * hp[h];
        vals[t] = hv; s += hv; ss += hv * hv;
    }
    __shared__ float red[16];
    #pragma unroll
    for (int o = 16; o; o >>= 1) {
        s  += __shfl_xor_sync(0xffffffffu, s, o);
        ss += __shfl_xor_sync(0xffffffffu, ss, o);
    }
    int w = threadIdx.x >> 5;
    if ((threadIdx.x & 31) == 0) { red[w] = s; red[8 + w] = ss; }
    __syncthreads();
    s = 0.f; ss = 0.f;
    #pragma unroll
    for (int i = 0; i < 8; i++) { s += red[i]; ss += red[8 + i]; }
    float mean = s * (1.f / Hd);
    float var  = ss * (1.f / Hd) - mean * mean;
    float rstd = rsqrtf(var + EPSv);
    #pragma unroll
    for (int t = 0; t < 4; t++) {
        int h = threadIdx.x + t * 256;
        float o = (vals[t] - mean) * rstd * ln_g[k * Hd + h] + ln_b[k * Hd + h];
        h_new[hBase + h]   = o;
        h_new_r[hBase + h] = to_tf32(o);
    }
}

// ---------------- attention over K=8 expert states ---------------------------
__global__ void attn_kernel(const float* __restrict__ q, const float* __restrict__ kmat,
                            const float* __restrict__ vmat, float* __restrict__ ctx,
                            float* __restrict__ ctx_r)
{
    const int b = blockIdx.x >> 2;
    const int n = blockIdx.x & 3;
    const int tid = threadIdx.x;
    const int lane = tid & 31, w = tid >> 5;
    __shared__ float sc[KE];
    const float* qp = q + (long)b * Hd + n * HDim;
    {
        const float* kp = kmat + (long)b * KE * Hd + (long)w * Hd + n * HDim;
        float s = 0.f;
        #pragma unroll
        for (int d = lane; d < HDim; d += 32) s += qp[d] * kp[d];
        #pragma unroll
        for (int o = 16; o; o >>= 1) s += __shfl_xor_sync(0xffffffffu, s, o);
        if (lane == 0) sc[w] = s * (1.0f / 16.0f);
    }
    __syncthreads();
    float e[KE], m = -1e30f;
    #pragma unroll
    for (int k = 0; k < KE; k++) m = fmaxf(m, sc[k]);
    float sum = 0.f;
    #pragma unroll
    for (int k = 0; k < KE; k++) { e[k] = expf(sc[k] - m); sum += e[k]; }
    float inv = 1.f / sum;
    float acc = 0.f;
    const float* vb = vmat + (long)b * KE * Hd + n * HDim + tid;
    #pragma unroll
    for (int k = 0; k < KE; k++) acc += e[k] * inv * vb[(long)k * Hd];
    ctx[(long)b * Hd + n * HDim + tid]   = acc;
    ctx_r[(long)b * Hd + n * HDim + tid] = to_tf32(acc);
}

// ---------------- residual add + LayerNorm -----------------------------------
__global__ void add_ln_kernel(const float* __restrict__ a, const float* __restrict__ bvec,
                              const float* __restrict__ g, const float* __restrict__ be,
                              float* __restrict__ out)
{
    const int b = blockIdx.x;
    const long base = (long)b * Hd;
    float vals[4]; float s = 0.f, ss = 0.f;
    #pragma unroll
    for (int t = 0; t < 4; t++) {
        int h = threadIdx.x + t * 256;
        float v = a[base + h] + bvec[base + h];
        vals[t] = v; s += v; ss += v * v;
    }
    __shared__ float red[16];
    #pragma unroll
    for (int o = 16; o; o >>= 1) {
        s  += __shfl_xor_sync(0xffffffffu, s, o);
        ss += __shfl_xor_sync(0xffffffffu, ss, o);
    }
    int w = threadIdx.x >> 5;
    if ((threadIdx.x & 31) == 0) { red[w] = s; red[8 + w] = ss; }
    __syncthreads();
    s = 0.f; ss = 0.f;
    #pragma unroll
    for (int i = 0; i < 8; i++) { s += red[i]; ss += red[8 + i]; }
    float mean = s * (1.f / Hd);
    float rstd = rsqrtf(ss * (1.f / Hd) - mean * mean + EPSv);
    #pragma unroll
    for (int t = 0; t < 4; t++) {
        int h = threadIdx.x + t * 256;
        out[base + h] = (vals[t] - mean) * rstd * g[h] + be[h];
    }
}

// ---------------- gate logits + softmax + expert mix -------------------------
__global__ void gate_mix_kernel(const float* __restrict__ context, const float* __restrict__ W_gate,
                                const float* __restrict__ b_gate, const float* __restrict__ h_new,
                                float* __restrict__ logits_out, float* __restrict__ gt_out,
                                float* __restrict__ mixed, float* __restrict__ mixed_r)
{
    const int b = blockIdx.x;
    const int tid = threadIdx.x, lane = tid & 31, w = tid >> 5;
    __shared__ float sl[KE];
    const float* cr = context + (long)b * Hd;
    {
        const float* wg = W_gate + (long)w * Hd;
        float s = 0.f;
        for (int h = lane; h < Hd; h += 32) s += cr[h] * wg[h];
        #pragma unroll
        for (int o = 16; o; o >>= 1) s += __shfl_xor_sync(0xffffffffu, s, o);
        if (lane == 0) sl[w] = s + b_gate[w];
    }
    __syncthreads();
    float lg[KE], m = -1e30f;
    #pragma unroll
    for (int k = 0; k < KE; k++) { lg[k] = sl[k]; m = fmaxf(m, lg[k]); }
    float e[KE], sum = 0.f;
    #pragma unroll
    for (int k = 0; k < KE; k++) { e[k] = expf(lg[k] - m); sum += e[k]; }
    float inv = 1.f / sum;
    if (tid < KE) {
        logits_out[(long)b * KE + tid] = lg[tid];
        gt_out[(long)b * KE + tid]     = e[tid] * inv;
    }
    const float* hb = h_new + (long)b * KE * Hd;
    #pragma unroll
    for (int t = 0; t < 4; t++) {
        int h = tid + t * 256;
        float acc = 0.f;
        #pragma unroll
        for (int k = 0; k < KE; k++) acc += e[k] * inv * hb[(long)k * Hd + h];
        mixed[(long)b * Hd + h]   = acc;
        mixed_r[(long)b * Hd + h] = to_tf32(acc);
    }
}

// ---------------- host orchestration -----------------------------------------
static void launch_round(const float* in, float* out, long n)
{
    int n4 = (int)(n / 4);
    round_tf32_kernel<<<(n4 + 255) / 256, 256>>>((const float4*)in, (float4*)out, n4);
}

static void launch_mma(const float* A, const float* Bm, const float* bias, float* C,
                       float* Cr, int M, int N, int Kd, int lda, int ldb, int ldc,
                       int batch, long aBat, long bBat, long cBat, long biasBat)
{
    dim3 grid(N / 128, M / 256, batch);
    mma_tn<<<grid, 256, SMEMB>>>(A, Bm, bias, C, Cr, Kd, lda, ldb, ldc,
                                 aBat, bBat, cBat, biasBat);
}

extern "C" void kernel_launch(void* const* d_in, const int* in_sizes, int n_in,
                              void* d_out, int out_size)
{
    const float* x_t     = (const float*)d_in[0];
    const float* h_prev  = (const float*)d_in[1];
    const float* W_ih    = (const float*)d_in[2];
    const float* W_hh    = (const float*)d_in[3];
    const float* b_ih    = (const float*)d_in[4];
    const float* b_hh    = (const float*)d_in[5];
    const float* ln_g    = (const float*)d_in[6];
    const float* ln_b    = (const float*)d_in[7];
    const float* Wq_proj = (const float*)d_in[8];
    const float* bq_proj = (const float*)d_in[9];
    const float* W_q     = (const float*)d_in[10];
    const float* W_k     = (const float*)d_in[11];
    const float* W_v     = (const float*)d_in[12];
    const float* b_q     = (const float*)d_in[13];
    const float* b_k     = (const float*)d_in[14];
    const float* b_v     = (const float*)d_in[15];
    const float* W_o     = (const float*)d_in[16];
    const float* b_o     = (const float*)d_in[17];
    const float* aln_g   = (const float*)d_in[18];
    const float* aln_b   = (const float*)d_in[19];
    const float* W_gate  = (const float*)d_in[20];
    const float* b_gate  = (const float*)d_in[21];
    const float* W_read  = (const float*)d_in[22];
    const float* b_read  = (const float*)d_in[23];

    float* out    = (float*)d_out;
    float* h_new  = out;                                   // (B,K,H)
    float* y_hat  = out + (long)Bsz * KE * Hd;             // (B,O)
    float* g_t    = y_hat + (long)Bsz * Oo;                // (B,K)
    float* logits = g_t + (long)Bsz * KE;                  // (B,K)

    float *gi, *gh, *query, *qm, *kmat, *vmat, *ctx, *attnout, *contextb, *mixed;
    float *xr, *hpr, *Wihr, *Whhr, *Wqpr, *Wqr, *Wkr, *Wvr, *Wor, *Wrdr;
    float *queryr, *hnewr, *ctxr, *mixedr;
    cudaGetSymbolAddress((void**)&gi, g_gi);
    cudaGetSymbolAddress((void**)&gh, g_gh);
    cudaGetSymbolAddress((void**)&query, g_query);
    cudaGetSymbolAddress((void**)&qm, g_q);
    cudaGetSymbolAddress((void**)&kmat, g_kmat);
    cudaGetSymbolAddress((void**)&vmat, g_vmat);
    cudaGetSymbolAddress((void**)&ctx, g_ctx);
    cudaGetSymbolAddress((void**)&attnout, g_attnout);
    cudaGetSymbolAddress((void**)&contextb, g_context);
    cudaGetSymbolAddress((void**)&mixed, g_mixed);
    cudaGetSymbolAddress((void**)&xr, g_xr);
    cudaGetSymbolAddress((void**)&hpr, g_hpr);
    cudaGetSymbolAddress((void**)&Wihr, g_Wihr);
    cudaGetSymbolAddress((void**)&Whhr, g_Whhr);
    cudaGetSymbolAddress((void**)&Wqpr, g_Wqpr);
    cudaGetSymbolAddress((void**)&Wqr, g_Wqr);
    cudaGetSymbolAddress((void**)&Wkr, g_Wkr);
    cudaGetSymbolAddress((void**)&Wvr, g_Wvr);
    cudaGetSymbolAddress((void**)&Wor, g_Wor);
    cudaGetSymbolAddress((void**)&Wrdr, g_Wrdr);
    cudaGetSymbolAddress((void**)&queryr, g_queryr);
    cudaGetSymbolAddress((void**)&hnewr, g_hnewr);
    cudaGetSymbolAddress((void**)&ctxr, g_ctxr);
    cudaGetSymbolAddress((void**)&mixedr, g_mixedr);

    cudaFuncSetAttribute(mma_tn, cudaFuncAttributeMaxDynamicSharedMemorySize, SMEMB);

    // 0) pre-round all harness-provided GEMM operands to tf32 values
    launch_round(x_t,     xr,   (long)Bsz * Din);
    launch_round(h_prev,  hpr,  (long)Bsz * KE * Hd);
    launch_round(W_ih,    Wihr, (long)KE * 3 * Hd * Din);
    launch_round(W_hh,    Whhr, (long)KE * 3 * Hd * Hd);
    launch_round(Wq_proj, Wqpr, (long)Hd * Din);
    launch_round(W_q,     Wqr,  (long)Hd * Hd);
    launch_round(W_k,     Wkr,  (long)Hd * Hd);
    launch_round(W_v,     Wvr,  (long)Hd * Hd);
    launch_round(W_o,     Wor,  (long)Hd * Hd);
    launch_round(W_read,  Wrdr, (long)Oo * Hd);

    // 1) gi = x_t @ W_ih^T + b_ih          (4096 x 24576 x 512)
    launch_mma(xr, Wihr, b_ih, gi, nullptr, Bsz, KE * 3 * Hd, Din,
               Din, Din, KE * 3 * Hd, 1, 0, 0, 0, 0);
    // 2) gh[k] = h_prev[:,k,:] @ W_hh[k]^T + b_hh[k]   (batched over K)
    launch_mma(hpr, Whhr, b_hh, gh, nullptr, Bsz, 3 * Hd, Hd,
               KE * Hd, Hd, KE * 3 * Hd, KE,
               (long)Hd, (long)3 * Hd * Hd, (long)3 * Hd, (long)3 * Hd);
    // 3) GRU pointwise + per-expert LN -> h_new (d_out) + rounded copy
    gru_ln_kernel<<<Bsz * KE, 256>>>(gi, gh, h_prev, ln_g, ln_b, h_new, hnewr);
    // 4) query = x_t @ Wq_proj^T + bq_proj   (+ rounded copy for step 5)
    launch_mma(xr, Wqpr, bq_proj, query, queryr, Bsz, Hd, Din,
               Din, Din, Hd, 1, 0, 0, 0, 0);
    // 5) q = query @ W_q^T + b_q
    launch_mma(queryr, Wqr, b_q, qm, nullptr, Bsz, Hd, Hd, Hd, Hd, Hd, 1, 0, 0, 0, 0);
    // 6) kmat = h_new @ W_k^T + b_k     (32768 x 1024 x 1024)
    launch_mma(hnewr, Wkr, b_k, kmat, nullptr, Bsz * KE, Hd, Hd, Hd, Hd, Hd, 1, 0, 0, 0, 0);
    // 7) vmat = h_new @ W_v^T + b_v
    launch_mma(hnewr, Wvr, b_v, vmat, nullptr, Bsz * KE, Hd, Hd, Hd, Hd, Hd, 1, 0, 0, 0, 0);
    // 8) attention -> ctx (+ rounded copy)
    attn_kernel<<<Bsz * NHh, 256>>>(qm, kmat, vmat, ctx, ctxr);
    // 9) attn_out = ctx @ W_o^T + b_o
    launch_mma(ctxr, Wor, b_o, attnout, nullptr, Bsz, Hd, Hd, Hd, Hd, Hd, 1, 0, 0, 0, 0);
    // 10) context = LN(query + attn_out)
    add_ln_kernel<<<Bsz, 256>>>(query, attnout, aln_g, aln_b, contextb);
    // 11) gate logits + softmax + mix (+ rounded mixed)
    gate_mix_kernel<<<Bsz, 256>>>(contextb, W_gate, b_gate, h_new, logits, g_t, mixed, mixedr);
    // 12) y_hat = mixed @ W_read^T + b_read
    launch_mma(mixedr, Wrdr, b_read, y_hat, nullptr, Bsz, Oo, Hd, Hd, Hd, Oo, 1, 0, 0, 0, 0);
}

// round 13
// speedup vs baseline: 1.6446x; 1.6446x over previous
#include <cuda_runtime.h>
#include <math.h>
#include <stdint.h>

#define Bsz  4096
#define Din  512
#define Hd   1024
#define KE   8
#define Oo   256
#define NHh  4
#define HDim 256
#define EPSv 1e-5f

// ---------------- scratch (device globals; no allocations allowed) ----------
__device__ float g_gi[(size_t)Bsz * KE * 3 * Hd];   // (B, K, 3H)
__device__ float g_gh[(size_t)Bsz * KE * 3 * Hd];   // (B, K, 3H)
__device__ float g_query[(size_t)Bsz * Hd];
__device__ float g_q[(size_t)Bsz * Hd];
__device__ float g_kmat[(size_t)Bsz * KE * Hd];
__device__ float g_vmat[(size_t)Bsz * KE * Hd];
__device__ float g_ctx[(size_t)Bsz * Hd];
__device__ float g_attnout[(size_t)Bsz * Hd];
__device__ float g_context[(size_t)Bsz * Hd];
__device__ float g_mixed[(size_t)Bsz * Hd];

// tf32-rounded operand copies (bit-identical to in-loop cvt results)
__device__ float g_xr[(size_t)Bsz * Din];
__device__ float g_hpr[(size_t)Bsz * KE * Hd];
__device__ float g_Wihr[(size_t)KE * 3 * Hd * Din];
__device__ float g_Whhr[(size_t)KE * 3 * Hd * Hd];
__device__ float g_Wqpr[(size_t)Hd * Din];
__device__ float g_Wqr[(size_t)Hd * Hd];
__device__ float g_Wkr[(size_t)Hd * Hd];
__device__ float g_Wvr[(size_t)Hd * Hd];
__device__ float g_Wor[(size_t)Hd * Hd];
__device__ float g_Wrdr[(size_t)Oo * Hd];
__device__ float g_queryr[(size_t)Bsz * Hd];
__device__ float g_hnewr[(size_t)Bsz * KE * Hd];
__device__ float g_ctxr[(size_t)Bsz * Hd];
__device__ float g_mixedr[(size_t)Bsz * Hd];

// ---------------- helpers ----------------------------------------------------
__device__ __forceinline__ float to_tf32(float x) {
    float r; asm("cvt.rna.tf32.f32 %0, %1;" : "=f"(r) : "f"(x)); return r;
}
__device__ __forceinline__ void mma16n8k8(float* c, const uint32_t* a, const uint32_t* b) {
    asm volatile("mma.sync.aligned.m16n8k8.row.col.f32.tf32.tf32.f32 "
        "{%0,%1,%2,%3}, {%4,%5,%6,%7}, {%8,%9}, {%0,%1,%2,%3};"
        : "+f"(c[0]), "+f"(c[1]), "+f"(c[2]), "+f"(c[3])
        : "r"(a[0]), "r"(a[1]), "r"(a[2]), "r"(a[3]), "r"(b[0]), "r"(b[1]));
}
__device__ __forceinline__ uint32_t smem_u32(const void* p) {
    uint32_t a;
    asm("{ .reg .u64 t; cvta.to.shared.u64 t, %1; cvt.u32.u64 %0, t; }" : "=r"(a) : "l"(p));
    return a;
}
__device__ __forceinline__ void cp_async16(uint32_t dst, const void* src) {
    asm volatile("cp.async.cg.shared.global [%0], [%1], 16;" :: "r"(dst), "l"(src));
}
#define CP_COMMIT()  asm volatile("cp.async.commit_group;" ::: "memory")
#define CP_WAIT(n)   asm volatile("cp.async.wait_group %0;" :: "n"(n) : "memory")

// ---------------- elementwise tf32 rounding ----------------------------------
__global__ void round_tf32_kernel(const float4* __restrict__ in, float4* __restrict__ out, int n4)
{
    int i = blockIdx.x * 256 + threadIdx.x;
    if (i < n4) {
        float4 v = in[i];
        v.x = to_tf32(v.x); v.y = to_tf32(v.y); v.z = to_tf32(v.z); v.w = to_tf32(v.w);
        out[i] = v;
    }
}

// ================= tf32 mma.sync TN GEMM (pre-rounded operands) ==============
// C[m,n] = sum_k A[m,k]*B[n,k] + bias[n]; A,B already tf32-valued fp32.
// Block 128x128, K-chunk 32, 256 threads (8 warps: 2M x 4N, warp tile 64x32).
// 3-stage cp.async, 2 CTAs/SM. Uniform group-count invariant: EVERY iteration
// commits exactly one group (empty in tail) so wait_group(1) provably retires
// chunk c's group, including the last chunk.
#define STG_W   4608                        // 128*36 words per matrix-stage
#define STAGE_W (2 * STG_W)                 // A + B per stage
#define NSTAGE  3
#define SMEMW   (NSTAGE * STAGE_W)
#define SMEMB   (SMEMW * 4)                 // 110592 bytes

__global__ __launch_bounds__(256, 2)
void mma_tn(const float* __restrict__ A, const float* __restrict__ Bm,
            const float* __restrict__ bias, float* __restrict__ C,
            float* __restrict__ Cr,          // optional tf32-rounded copy of C
            int Kd, int lda, int ldb, int ldc,
            long aBat, long bBat, long cBat, long biasBat)
{
    extern __shared__ float smf[];
    const int tid  = threadIdx.x;
    const int wid  = tid >> 5;
    const int lane = tid & 31;
    const int warpM = wid & 1;        // 0..1  (64 rows each)
    const int warpN = wid >> 1;       // 0..3  (32 cols each)
    const int r = lane >> 2;          // 0..7
    const int q = lane & 3;           // 0..3

    const int bz = blockIdx.z;
    A  += (long)bz * aBat;
    Bm += (long)bz * bBat;
    C  += (long)bz * cBat;
    const float* biasp = bias ? bias + (long)bz * biasBat : nullptr;

    const int rowBase = blockIdx.y * 128;
    const int colBase = blockIdx.x * 128;

    const int lrow = tid >> 3;        // 0..31 -> covers 128 rows via i*32
    const int lc4  = (tid & 7) * 4;   // 0,4,...,28

    const uint32_t smb = smem_u32(smf);

    // issue cp.async for one 32-wide K chunk into stage s (one group)
    auto issue_chunk = [&](int k0, int s) {
        const uint32_t as = smb + (s * STAGE_W) * 4;
        const uint32_t bs = as + STG_W * 4;
        const uint32_t soff = (lrow * 36 + lc4) * 4;
        #pragma unroll
        for (int i = 0; i < 4; i++) {
            int row = lrow + i * 32;
            cp_async16(as + soff + i * (32 * 36 * 4),
                       A + (long)(rowBase + row) * lda + k0 + lc4);
            cp_async16(bs + soff + i * (32 * 36 * 4),
                       Bm + (long)(colBase + row) * ldb + k0 + lc4);
        }
        CP_COMMIT();
    };

    float acc[4][4][4];
    #pragma unroll
    for (int mt = 0; mt < 4; mt++)
        #pragma unroll
        for (int nt = 0; nt < 4; nt++)
            #pragma unroll
            for (int j = 0; j < 4; j++) acc[mt][nt][j] = 0.0f;

    const int NC = Kd >> 5;

    // prologue: prefetch chunks 0 and 1 -> groups G0, G1
    issue_chunk(0, 0);
    if (NC > 1) issue_chunk(32, 1);
    else        CP_COMMIT();          // keep group-count invariant for NC==1

    for (int c = 0; c < NC; c++) {
        const int s = c % NSTAGE;
        CP_WAIT(1);                   // newest group is G(c+1) -> G(c) retired
        __syncthreads();

        const float* as = smf + s * STAGE_W + (warpM * 64) * 36;
        const float* bs = smf + s * STAGE_W + STG_W + (warpN * 32) * 36;

        #pragma unroll
        for (int ks = 0; ks < 4; ks++) {
            const int k0 = ks * 8;
            uint32_t afr[4][4], bfr[4][2];
            #pragma unroll
            for (int mt = 0; mt < 4; mt++) {
                const float* ap = as + (mt * 16 + r) * 36 + k0 + q;
                afr[mt][0] = __float_as_uint(ap[0]);
                afr[mt][1] = __float_as_uint(ap[8 * 36]);
                afr[mt][2] = __float_as_uint(ap[4]);
                afr[mt][3] = __float_as_uint(ap[8 * 36 + 4]);
            }
            #pragma unroll
            for (int nt = 0; nt < 4; nt++) {
                const float* bp = bs + (nt * 8 + r) * 36 + k0 + q;
                bfr[nt][0] = __float_as_uint(bp[0]);
                bfr[nt][1] = __float_as_uint(bp[4]);
            }
            #pragma unroll
            for (int mt = 0; mt < 4; mt++)
                #pragma unroll
                for (int nt = 0; nt < 4; nt++)
                    mma16n8k8(acc[mt][nt], afr[mt], bfr[nt]);
        }

        // issue next prefetch (or an EMPTY group to keep counts uniform)
        if (c + NSTAGE - 1 < NC)
            issue_chunk((c + NSTAGE - 1) * 32, (c + NSTAGE - 1) % NSTAGE);
        else
            CP_COMMIT();
        __syncthreads();
    }

    // ---- epilogue: acc -> C (+bias), optional rounded copy ----
    #pragma unroll
    for (int mt = 0; mt < 4; mt++) {
        const int row = rowBase + warpM * 64 + mt * 16 + r;
        #pragma unroll
        for (int nt = 0; nt < 4; nt++) {
            const int col = colBase + warpN * 32 + nt * 8 + q * 2;
            float b0 = 0.f, b1 = 0.f;
            if (biasp) { b0 = biasp[col]; b1 = biasp[col + 1]; }
            float2 v0, v1;
            v0.x = acc[mt][nt][0] + b0; v0.y = acc[mt][nt][1] + b1;
            v1.x = acc[mt][nt][2] + b0; v1.y = acc[mt][nt][3] + b1;
            *(float2*)(C + (long)row * ldc + col)       = v0;
            *(float2*)(C + (long)(row + 8) * ldc + col) = v1;
            if (Cr) {
                float2 r0, r1;
                r0.x = to_tf32(v0.x); r0.y = to_tf32(v0.y);
                r1.x = to_tf32(v1.x); r1.y = to_tf32(v1.y);
                *(float2*)(Cr + (long)row * ldc + col)       = r0;
                *(float2*)(Cr + (long)(row + 8) * ldc + col) = r1;
            }
        }
    }
}

// ---------------- GRU pointwise + per-expert LayerNorm -----------------------
__global__ void gru_ln_kernel(const float* __restrict__ gi, const float* __restrict__ gh,
                              const float* __restrict__ h_prev,
                              const float* __restrict__ ln_g, const float* __restrict__ ln_b,
                              float* __restrict__ h_new, float* __restrict__ h_new_r)
{
    const int bk = blockIdx.x;
    const int k  = bk & (KE - 1);
    const long giBase = (long)bk * (3 * Hd);
    const long hBase  = (long)bk * Hd;
    const float* gir = gi + giBase;
    const float* ghr = gh + giBase;
    const float* hp  = h_prev + hBase;

    float vals[4];
    float s = 0.f, ss = 0.f;
    #pragma unroll
    for (int t = 0; t < 4; t++) {
        int h = threadIdx.x + t * 256;
        float ir = gir[h],           hr = ghr[h];
        float iz = gir[Hd + h],      hz = ghr[Hd + h];
        float inn = gir[2 * Hd + h], hn = ghr[2 * Hd + h];
        float r = 1.f / (1.f + expf(-(ir + hr)));
        float z = 1.f / (1.f + expf(-(iz + hz)));
        float n = tanhf(inn + r * hn);
        float hv = (1.f - z) * n + z * hp[h];
        vals[t] = hv; s += hv; ss += hv * hv;
    }
    __shared__ float red[16];
    #pragma unroll
    for (int o = 16; o; o >>= 1) {
        s  += __shfl_xor_sync(0xffffffffu, s, o);
        ss += __shfl_xor_sync(0xffffffffu, ss, o);
    }
    int w = threadIdx.x >> 5;
    if ((threadIdx.x & 31) == 0) { red[w] = s; red[8 + w] = ss; }
    __syncthreads();
    s = 0.f; ss = 0.f;
    #pragma unroll
    for (int i = 0; i < 8; i++) { s += red[i]; ss += red[8 + i]; }
    float mean = s * (1.f / Hd);
    float var  = ss * (1.f / Hd) - mean * mean;
    float rstd = rsqrtf(var + EPSv);
    #pragma unroll
    for (int t = 0; t < 4; t++) {
        int h = threadIdx.x + t * 256;
        float o = (vals[t] - mean) * rstd * ln_g[k * Hd + h] + ln_b[k * Hd + h];
        h_new[hBase + h]   = o;
        h_new_r[hBase + h] = to_tf32(o);
    }
}

// ---------------- attention over K=8 expert states ---------------------------
__global__ void attn_kernel(const float* __restrict__ q, const float* __restrict__ kmat,
                            const float* __restrict__ vmat, float* __restrict__ ctx,
                            float* __restrict__ ctx_r)
{
    const int b = blockIdx.x >> 2;
    const int n = blockIdx.x & 3;
    const int tid = threadIdx.x;
    const int lane = tid & 31, w = tid >> 5;
    __shared__ float sc[KE];
    const float* qp = q + (long)b * Hd + n * HDim;
    {
        const float* kp = kmat + (long)b * KE * Hd + (long)w * Hd + n * HDim;
        float s = 0.f;
        #pragma unroll
        for (int d = lane; d < HDim; d += 32) s += qp[d] * kp[d];
        #pragma unroll
        for (int o = 16; o; o >>= 1) s += __shfl_xor_sync(0xffffffffu, s, o);
        if (lane == 0) sc[w] = s * (1.0f / 16.0f);
    }
    __syncthreads();
    float e[KE], m = -1e30f;
    #pragma unroll
    for (int k = 0; k < KE; k++) m = fmaxf(m, sc[k]);
    float sum = 0.f;
    #pragma unroll
    for (int k = 0; k < KE; k++) { e[k] = expf(sc[k] - m); sum += e[k]; }
    float inv = 1.f / sum;
    float acc = 0.f;
    const float* vb = vmat + (long)b * KE * Hd + n * HDim + tid;
    #pragma unroll
    for (int k = 0; k < KE; k++) acc += e[k] * inv * vb[(long)k * Hd];
    ctx[(long)b * Hd + n * HDim + tid]   = acc;
    ctx_r[(long)b * Hd + n * HDim + tid] = to_tf32(acc);
}

// ---------------- residual add + LayerNorm -----------------------------------
__global__ void add_ln_kernel(const float* __restrict__ a, const float* __restrict__ bvec,
                              const float* __restrict__ g, const float* __restrict__ be,
                              float* __restrict__ out)
{
    const int b = blockIdx.x;
    const long base = (long)b * Hd;
    float vals[4]; float s = 0.f, ss = 0.f;
    #pragma unroll
    for (int t = 0; t < 4; t++) {
        int h = threadIdx.x + t * 256;
        float v = a[base + h] + bvec[base + h];
        vals[t] = v; s += v; ss += v * v;
    }
    __shared__ float red[16];
    #pragma unroll
    for (int o = 16; o; o >>= 1) {
        s  += __shfl_xor_sync(0xffffffffu, s, o);
        ss += __shfl_xor_sync(0xffffffffu, ss, o);
    }
    int w = threadIdx.x >> 5;
    if ((threadIdx.x & 31) == 0) { red[w] = s; red[8 + w] = ss; }
    __syncthreads();
    s = 0.f; ss = 0.f;
    #pragma unroll
    for (int i = 0; i < 8; i++) { s += red[i]; ss += red[8 + i]; }
    float mean = s * (1.f / Hd);
    float rstd = rsqrtf(ss * (1.f / Hd) - mean * mean + EPSv);
    #pragma unroll
    for (int t = 0; t < 4; t++) {
        int h = threadIdx.x + t * 256;
        out[base + h] = (vals[t] - mean) * rstd * g[h] + be[h];
    }
}

// ---------------- gate logits + softmax + expert mix -------------------------
__global__ void gate_mix_kernel(const float* __restrict__ context, const float* __restrict__ W_gate,
                                const float* __restrict__ b_gate, const float* __restrict__ h_new,
                                float* __restrict__ logits_out, float* __restrict__ gt_out,
                                float* __restrict__ mixed, float* __restrict__ mixed_r)
{
    const int b = blockIdx.x;
    const int tid = threadIdx.x, lane = tid & 31, w = tid >> 5;
    __shared__ float sl[KE];
    const float* cr = context + (long)b * Hd;
    {
        const float* wg = W_gate + (long)w * Hd;
        float s = 0.f;
        for (int h = lane; h < Hd; h += 32) s += cr[h] * wg[h];
        #pragma unroll
        for (int o = 16; o; o >>= 1) s += __shfl_xor_sync(0xffffffffu, s, o);
        if (lane == 0) sl[w] = s + b_gate[w];
    }
    __syncthreads();
    float lg[KE], m = -1e30f;
    #pragma unroll
    for (int k = 0; k < KE; k++) { lg[k] = sl[k]; m = fmaxf(m, lg[k]); }
    float e[KE], sum = 0.f;
    #pragma unroll
    for (int k = 0; k < KE; k++) { e[k] = expf(lg[k] - m); sum += e[k]; }
    float inv = 1.f / sum;
    if (tid < KE) {
        logits_out[(long)b * KE + tid] = lg[tid];
        gt_out[(long)b * KE + tid]     = e[tid] * inv;
    }
    const float* hb = h_new + (long)b * KE * Hd;
    #pragma unroll
    for (int t = 0; t < 4; t++) {
        int h = tid + t * 256;
        float acc = 0.f;
        #pragma unroll
        for (int k = 0; k < KE; k++) acc += e[k] * inv * hb[(long)k * Hd + h];
        mixed[(long)b * Hd + h]   = acc;
        mixed_r[(long)b * Hd + h] = to_tf32(acc);
    }
}

// ---------------- host orchestration -----------------------------------------
static void launch_round(const float* in, float* out, long n)
{
    int n4 = (int)(n / 4);
    round_tf32_kernel<<<(n4 + 255) / 256, 256>>>((const float4*)in, (float4*)out, n4);
}

static void launch_mma(const float* A, const float* Bm, const float* bias, float* C,
                       float* Cr, int M, int N, int Kd, int lda, int ldb, int ldc,
                       int batch, long aBat, long bBat, long cBat, long biasBat)
{
    dim3 grid(N / 128, M / 128, batch);
    mma_tn<<<grid, 256, SMEMB>>>(A, Bm, bias, C, Cr, Kd, lda, ldb, ldc,
                                 aBat, bBat, cBat, biasBat);
}

extern "C" void kernel_launch(void* const* d_in, const int* in_sizes, int n_in,
                              void* d_out, int out_size)
{
    const float* x_t     = (const float*)d_in[0];
    const float* h_prev  = (const float*)d_in[1];
    const float* W_ih    = (const float*)d_in[2];
    const float* W_hh    = (const float*)d_in[3];
    const float* b_ih    = (const float*)d_in[4];
    const float* b_hh    = (const float*)d_in[5];
    const float* ln_g    = (const float*)d_in[6];
    const float* ln_b    = (const float*)d_in[7];
    const float* Wq_proj = (const float*)d_in[8];
    const float* bq_proj = (const float*)d_in[9];
    const float* W_q     = (const float*)d_in[10];
    const float* W_k     = (const float*)d_in[11];
    const float* W_v     = (const float*)d_in[12];
    const float* b_q     = (const float*)d_in[13];
    const float* b_k     = (const float*)d_in[14];
    const float* b_v     = (const float*)d_in[15];
    const float* W_o     = (const float*)d_in[16];
    const float* b_o     = (const float*)d_in[17];
    const float* aln_g   = (const float*)d_in[18];
    const float* aln_b   = (const float*)d_in[19];
    const float* W_gate  = (const float*)d_in[20];
    const float* b_gate  = (const float*)d_in[21];
    const float* W_read  = (const float*)d_in[22];
    const float* b_read  = (const float*)d_in[23];

    float* out    = (float*)d_out;
    float* h_new  = out;                                   // (B,K,H)
    float* y_hat  = out + (long)Bsz * KE * Hd;             // (B,O)
    float* g_t    = y_hat + (long)Bsz * Oo;                // (B,K)
    float* logits = g_t + (long)Bsz * KE;                  // (B,K)

    float *gi, *gh, *query, *qm, *kmat, *vmat, *ctx, *attnout, *contextb, *mixed;
    float *xr, *hpr, *Wihr, *Whhr, *Wqpr, *Wqr, *Wkr, *Wvr, *Wor, *Wrdr;
    float *queryr, *hnewr, *ctxr, *mixedr;
    cudaGetSymbolAddress((void**)&gi, g_gi);
    cudaGetSymbolAddress((void**)&gh, g_gh);
    cudaGetSymbolAddress((void**)&query, g_query);
    cudaGetSymbolAddress((void**)&qm, g_q);
    cudaGetSymbolAddress((void**)&kmat, g_kmat);
    cudaGetSymbolAddress((void**)&vmat, g_vmat);
    cudaGetSymbolAddress((void**)&ctx, g_ctx);
    cudaGetSymbolAddress((void**)&attnout, g_attnout);
    cudaGetSymbolAddress((void**)&contextb, g_context);
    cudaGetSymbolAddress((void**)&mixed, g_mixed);
    cudaGetSymbolAddress((void**)&xr, g_xr);
    cudaGetSymbolAddress((void**)&hpr, g_hpr);
    cudaGetSymbolAddress((void**)&Wihr, g_Wihr);
    cudaGetSymbolAddress((void**)&Whhr, g_Whhr);
    cudaGetSymbolAddress((void**)&Wqpr, g_Wqpr);
    cudaGetSymbolAddress((void**)&Wqr, g_Wqr);
    cudaGetSymbolAddress((void**)&Wkr, g_Wkr);
    cudaGetSymbolAddress((void**)&Wvr, g_Wvr);
    cudaGetSymbolAddress((void**)&Wor, g_Wor);
    cudaGetSymbolAddress((void**)&Wrdr, g_Wrdr);
    cudaGetSymbolAddress((void**)&queryr, g_queryr);
    cudaGetSymbolAddress((void**)&hnewr, g_hnewr);
    cudaGetSymbolAddress((void**)&ctxr, g_ctxr);
    cudaGetSymbolAddress((void**)&mixedr, g_mixedr);

    cudaFuncSetAttribute(mma_tn, cudaFuncAttributeMaxDynamicSharedMemorySize, SMEMB);

    // 0) pre-round all harness-provided GEMM operands to tf32 values
    launch_round(x_t,     xr,   (long)Bsz * Din);
    launch_round(h_prev,  hpr,  (long)Bsz * KE * Hd);
    launch_round(W_ih,    Wihr, (long)KE * 3 * Hd * Din);
    launch_round(W_hh,    Whhr, (long)KE * 3 * Hd * Hd);
    launch_round(Wq_proj, Wqpr, (long)Hd * Din);
    launch_round(W_q,     Wqr,  (long)Hd * Hd);
    launch_round(W_k,     Wkr,  (long)Hd * Hd);
    launch_round(W_v,     Wvr,  (long)Hd * Hd);
    launch_round(W_o,     Wor,  (long)Hd * Hd);
    launch_round(W_read,  Wrdr, (long)Oo * Hd);

    // 1) gi = x_t @ W_ih^T + b_ih          (4096 x 24576 x 512)
    launch_mma(xr, Wihr, b_ih, gi, nullptr, Bsz, KE * 3 * Hd, Din,
               Din, Din, KE * 3 * Hd, 1, 0, 0, 0, 0);
    // 2) gh[k] = h_prev[:,k,:] @ W_hh[k]^T + b_hh[k]   (batched over K)
    launch_mma(hpr, Whhr, b_hh, gh, nullptr, Bsz, 3 * Hd, Hd,
               KE * Hd, Hd, KE * 3 * Hd, KE,
               (long)Hd, (long)3 * Hd * Hd, (long)3 * Hd, (long)3 * Hd);
    // 3) GRU pointwise + per-expert LN -> h_new (d_out) + rounded copy
    gru_ln_kernel<<<Bsz * KE, 256>>>(gi, gh, h_prev, ln_g, ln_b, h_new, hnewr);
    // 4) query = x_t @ Wq_proj^T + bq_proj   (+ rounded copy for step 5)
    launch_mma(xr, Wqpr, bq_proj, query, queryr, Bsz, Hd, Din,
               Din, Din, Hd, 1, 0, 0, 0, 0);
    // 5) q = query @ W_q^T + b_q
    launch_mma(queryr, Wqr, b_q, qm, nullptr, Bsz, Hd, Hd, Hd, Hd, Hd, 1, 0, 0, 0, 0);
    // 6) kmat = h_new @ W_k^T + b_k     (32768 x 1024 x 1024)
    launch_mma(hnewr, Wkr, b_k, kmat, nullptr, Bsz * KE, Hd, Hd, Hd, Hd, Hd, 1, 0, 0, 0, 0);
    // 7) vmat = h_new @ W_v^T + b_v
    launch_mma(hnewr, Wvr, b_v, vmat, nullptr, Bsz * KE, Hd, Hd, Hd, Hd, Hd, 1, 0, 0, 0, 0);
    // 8) attention -> ctx (+ rounded copy)
    attn_kernel<<<Bsz * NHh, 256>>>(qm, kmat, vmat, ctx, ctxr);
    // 9) attn_out = ctx @ W_o^T + b_o
    launch_mma(ctxr, Wor, b_o, attnout, nullptr, Bsz, Hd, Hd, Hd, Hd, Hd, 1, 0, 0, 0, 0);
    // 10) context = LN(query + attn_out)
    add_ln_kernel<<<Bsz, 256>>>(query, attnout, aln_g, aln_b, contextb);
    // 11) gate logits + softmax + mix (+ rounded mixed)
    gate_mix_kernel<<<Bsz, 256>>>(contextb, W_gate, b_gate, h_new, logits, g_t, mixed, mixedr);
    // 12) y_hat = mixed @ W_read^T + b_read
    launch_mma(mixedr, Wrdr, b_read, y_hat, nullptr, Bsz, Oo, Hd, Hd, Hd, Oo, 1, 0, 0, 0, 0);
}

// round 15
// speedup vs baseline: 2.4004x; 1.4595x over previous
#include <cuda_runtime.h>
#include <cuda_fp16.h>
#include <math.h>
#include <stdint.h>

#define Bsz  4096
#define Din  512
#define Hd   1024
#define KE   8
#define Oo   256
#define NHh  4
#define HDim 256
#define EPSv 1e-5f

// ---------------- scratch (device globals; no allocations allowed) ----------
__device__ float g_gi[(size_t)Bsz * KE * 3 * Hd];   // (B, K, 3H)
__device__ float g_gh[(size_t)Bsz * KE * 3 * Hd];   // (B, K, 3H)
__device__ float g_query[(size_t)Bsz * Hd];
__device__ float g_q[(size_t)Bsz * Hd];
__device__ float g_kmat[(size_t)Bsz * KE * Hd];
__device__ float g_vmat[(size_t)Bsz * KE * Hd];
__device__ float g_ctx[(size_t)Bsz * Hd];
__device__ float g_attnout[(size_t)Bsz * Hd];
__device__ float g_context[(size_t)Bsz * Hd];
__device__ float g_mixed[(size_t)Bsz * Hd];

// fp16 operand copies (GEMM inputs)
__device__ __half g_xr[(size_t)Bsz * Din];
__device__ __half g_hpr[(size_t)Bsz * KE * Hd];
__device__ __half g_Wihr[(size_t)KE * 3 * Hd * Din];
__device__ __half g_Whhr[(size_t)KE * 3 * Hd * Hd];
__device__ __half g_Wqpr[(size_t)Hd * Din];
__device__ __half g_Wqr[(size_t)Hd * Hd];
__device__ __half g_Wkr[(size_t)Hd * Hd];
__device__ __half g_Wvr[(size_t)Hd * Hd];
__device__ __half g_Wor[(size_t)Hd * Hd];
__device__ __half g_Wrdr[(size_t)Oo * Hd];
__device__ __half g_queryr[(size_t)Bsz * Hd];
__device__ __half g_hnewr[(size_t)Bsz * KE * Hd];
__device__ __half g_ctxr[(size_t)Bsz * Hd];
__device__ __half g_mixedr[(size_t)Bsz * Hd];

// ---------------- helpers ----------------------------------------------------
__device__ __forceinline__ void mma16n8k16(float* c, const uint32_t* a, const uint32_t* b) {
    asm volatile("mma.sync.aligned.m16n8k16.row.col.f32.f16.f16.f32 "
        "{%0,%1,%2,%3}, {%4,%5,%6,%7}, {%8,%9}, {%0,%1,%2,%3};"
        : "+f"(c[0]), "+f"(c[1]), "+f"(c[2]), "+f"(c[3])
        : "r"(a[0]), "r"(a[1]), "r"(a[2]), "r"(a[3]), "r"(b[0]), "r"(b[1]));
}
__device__ __forceinline__ uint32_t smem_u32(const void* p) {
    uint32_t a;
    asm("{ .reg .u64 t; cvta.to.shared.u64 t, %1; cvt.u32.u64 %0, t; }" : "=r"(a) : "l"(p));
    return a;
}
__device__ __forceinline__ void cp_async16(uint32_t dst, const void* src) {
    asm volatile("cp.async.cg.shared.global [%0], [%1], 16;" :: "r"(dst), "l"(src));
}
#define CP_COMMIT()  asm volatile("cp.async.commit_group;" ::: "memory")
#define CP_WAIT(n)   asm volatile("cp.async.wait_group %0;" :: "n"(n) : "memory")

// ---------------- elementwise fp32 -> fp16 rounding --------------------------
__global__ void round_f16_kernel(const float4* __restrict__ in, uint4* __restrict__ out, int n8)
{
    int i = blockIdx.x * 256 + threadIdx.x;
    if (i < n8) {
        float4 a = in[2 * i], b = in[2 * i + 1];
        union { uint4 u; __half2 h[4]; } o;
        o.h[0] = __floats2half2_rn(a.x, a.y);
        o.h[1] = __floats2half2_rn(a.z, a.w);
        o.h[2] = __floats2half2_rn(b.x, b.y);
        o.h[3] = __floats2half2_rn(b.z, b.w);
        out[i] = o.u;
    }
}

// ================= fp16 mma.sync TN GEMM =====================================
// C[m,n] = sum_k A[m,k]*B[n,k] + bias[n]; A,B fp16, accumulate fp32.
// Block 128x128, K-chunk 32, 256 threads (8 warps: 2M x 4N, warp tile 64x32).
// Smem stage: A 128x32h + B 128x32h, row stride 40 halves (conflict-free).
// 3-stage cp.async, 2 CTAs/SM. Uniform group-count invariant: EVERY iteration
// commits exactly one group (empty in tail) so wait_group(1) provably retires
// chunk c's group, including the last chunk.
#define ROW_H   40                          // halves per smem row (32 data + 8 pad)
#define A_STG_H (128 * ROW_H)               // halves per matrix-stage
#define STAGE_H (2 * A_STG_H)               // A + B per stage
#define NSTAGE  3
#define SMEMB   (NSTAGE * STAGE_H * 2)      // 61440 bytes

__global__ __launch_bounds__(256, 2)
void mma_tn(const __half* __restrict__ A, const __half* __restrict__ Bm,
            const float* __restrict__ bias, float* __restrict__ C,
            __half* __restrict__ Cr,         // optional fp16-rounded copy of C
            int Kd, int lda, int ldb, int ldc,
            long aBat, long bBat, long cBat, long biasBat)
{
    extern __shared__ __half smh[];
    const int tid  = threadIdx.x;
    const int wid  = tid >> 5;
    const int lane = tid & 31;
    const int warpM = wid & 1;        // 0..1  (64 rows each)
    const int warpN = wid >> 1;       // 0..3  (32 cols each)
    const int r = lane >> 2;          // 0..7
    const int q = lane & 3;           // 0..3

    const int bz = blockIdx.z;
    A  += (long)bz * aBat;
    Bm += (long)bz * bBat;
    C  += (long)bz * cBat;
    const float* biasp = bias ? bias + (long)bz * biasBat : nullptr;

    const int rowBase = blockIdx.y * 128;
    const int colBase = blockIdx.x * 128;

    const int lrow = tid >> 2;        // 0..63 -> covers 128 rows via i*64
    const int lk8  = (tid & 3) * 8;   // 0,8,16,24 (halves)

    const uint32_t smb = smem_u32(smh);

    // issue cp.async for one 32-wide K chunk into stage s (one group)
    auto issue_chunk = [&](int k0, int s) {
        const uint32_t abase = smb + s * (STAGE_H * 2);
        const uint32_t bbase = abase + A_STG_H * 2;
        #pragma unroll
        for (int i = 0; i < 2; i++) {
            int row = lrow + i * 64;
            cp_async16(abase + (row * ROW_H + lk8) * 2,
                       A + (long)(rowBase + row) * lda + k0 + lk8);
            cp_async16(bbase + (row * ROW_H + lk8) * 2,
                       Bm + (long)(colBase + row) * ldb + k0 + lk8);
        }
        CP_COMMIT();
    };

    float acc[4][4][4];
    #pragma unroll
    for (int mt = 0; mt < 4; mt++)
        #pragma unroll
        for (int nt = 0; nt < 4; nt++)
            #pragma unroll
            for (int j = 0; j < 4; j++) acc[mt][nt][j] = 0.0f;

    const int NC = Kd >> 5;

    // prologue: prefetch chunks 0 and 1 -> groups G0, G1
    issue_chunk(0, 0);
    if (NC > 1) issue_chunk(32, 1);
    else        CP_COMMIT();          // keep group-count invariant for NC==1

    for (int c = 0; c < NC; c++) {
        const int s = c % NSTAGE;
        CP_WAIT(1);                   // newest group is G(c+1) -> G(c) retired
        __syncthreads();

        const __half* as = smh + s * STAGE_H + (warpM * 64) * ROW_H;
        const __half* bs = smh + s * STAGE_H + A_STG_H + (warpN * 32) * ROW_H;

        #pragma unroll
        for (int ks = 0; ks < 2; ks++) {
            const int k0h = ks * 16;
            uint32_t afr[4][4], bfr[4][2];
            #pragma unroll
            for (int mt = 0; mt < 4; mt++) {
                const __half* ap = as + (mt * 16 + r) * ROW_H + k0h + 2 * q;
                afr[mt][0] = *(const uint32_t*)(ap);
                afr[mt][1] = *(const uint32_t*)(ap + 8 * ROW_H);
                afr[mt][2] = *(const uint32_t*)(ap + 8);
                afr[mt][3] = *(const uint32_t*)(ap + 8 * ROW_H + 8);
            }
            #pragma unroll
            for (int nt = 0; nt < 4; nt++) {
                const __half* bp = bs + (nt * 8 + r) * ROW_H + k0h + 2 * q;
                bfr[nt][0] = *(const uint32_t*)(bp);
                bfr[nt][1] = *(const uint32_t*)(bp + 8);
            }
            #pragma unroll
            for (int mt = 0; mt < 4; mt++)
                #pragma unroll
                for (int nt = 0; nt < 4; nt++)
                    mma16n8k16(acc[mt][nt], afr[mt], bfr[nt]);
        }

        // issue next prefetch (or an EMPTY group to keep counts uniform)
        if (c + NSTAGE - 1 < NC)
            issue_chunk((c + NSTAGE - 1) * 32, (c + NSTAGE - 1) % NSTAGE);
        else
            CP_COMMIT();
        __syncthreads();
    }

    // ---- epilogue: acc -> C (+bias), optional fp16 copy ----
    #pragma unroll
    for (int mt = 0; mt < 4; mt++) {
        const int row = rowBase + warpM * 64 + mt * 16 + r;
        #pragma unroll
        for (int nt = 0; nt < 4; nt++) {
            const int col = colBase + warpN * 32 + nt * 8 + q * 2;
            float b0 = 0.f, b1 = 0.f;
            if (biasp) { b0 = biasp[col]; b1 = biasp[col + 1]; }
            float2 v0, v1;
            v0.x = acc[mt][nt][0] + b0; v0.y = acc[mt][nt][1] + b1;
            v1.x = acc[mt][nt][2] + b0; v1.y = acc[mt][nt][3] + b1;
            *(float2*)(C + (long)row * ldc + col)       = v0;
            *(float2*)(C + (long)(row + 8) * ldc + col) = v1;
            if (Cr) {
                *(__half2*)(Cr + (long)row * ldc + col)       = __floats2half2_rn(v0.x, v0.y);
                *(__half2*)(Cr + (long)(row + 8) * ldc + col) = __floats2half2_rn(v1.x, v1.y);
            }
        }
    }
}

// ---------------- GRU pointwise + per-expert LayerNorm -----------------------
__global__ void gru_ln_kernel(const float* __restrict__ gi, const float* __restrict__ gh,
                              const float* __restrict__ h_prev,
                              const float* __restrict__ ln_g, const float* __restrict__ ln_b,
                              float* __restrict__ h_new, __half* __restrict__ h_new_r)
{
    const int bk = blockIdx.x;
    const int k  = bk & (KE - 1);
    const long giBase = (long)bk * (3 * Hd);
    const long hBase  = (long)bk * Hd;
    const float* gir = gi + giBase;
    const float* ghr = gh + giBase;
    const float* hp  = h_prev + hBase;

    float vals[4];
    float s = 0.f, ss = 0.f;
    #pragma unroll
    for (int t = 0; t < 4; t++) {
        int h = threadIdx.x + t * 256;
        float ir = gir[h],           hr = ghr[h];
        float iz = gir[Hd + h],      hz = ghr[Hd + h];
        float inn = gir[2 * Hd + h], hn = ghr[2 * Hd + h];
        float r = 1.f / (1.f + expf(-(ir + hr)));
        float z = 1.f / (1.f + expf(-(iz + hz)));
        float n = tanhf(inn + r * hn);
        float hv = (1.f - z) * n + z * hp[h];
        vals[t] = hv; s += hv; ss += hv * hv;
    }
    __shared__ float red[16];
    #pragma unroll
    for (int o = 16; o; o >>= 1) {
        s  += __shfl_xor_sync(0xffffffffu, s, o);
        ss += __shfl_xor_sync(0xffffffffu, ss, o);
    }
    int w = threadIdx.x >> 5;
    if ((threadIdx.x & 31) == 0) { red[w] = s; red[8 + w] = ss; }
    __syncthreads();
    s = 0.f; ss = 0.f;
    #pragma unroll
    for (int i = 0; i < 8; i++) { s += red[i]; ss += red[8 + i]; }
    float mean = s * (1.f / Hd);
    float var  = ss * (1.f / Hd) - mean * mean;
    float rstd = rsqrtf(var + EPSv);
    #pragma unroll
    for (int t = 0; t < 4; t++) {
        int h = threadIdx.x + t * 256;
        float o = (vals[t] - mean) * rstd * ln_g[k * Hd + h] + ln_b[k * Hd + h];
        h_new[hBase + h]   = o;
        h_new_r[hBase + h] = __float2half_rn(o);
    }
}

// ---------------- attention over K=8 expert states ---------------------------
__global__ void attn_kernel(const float* __restrict__ q, const float* __restrict__ kmat,
                            const float* __restrict__ vmat, float* __restrict__ ctx,
                            __half* __restrict__ ctx_r)
{
    const int b = blockIdx.x >> 2;
    const int n = blockIdx.x & 3;
    const int tid = threadIdx.x;
    const int lane = tid & 31, w = tid >> 5;
    __shared__ float sc[KE];
    const float* qp = q + (long)b * Hd + n * HDim;
    {
        const float* kp = kmat + (long)b * KE * Hd + (long)w * Hd + n * HDim;
        float s = 0.f;
        #pragma unroll
        for (int d = lane; d < HDim; d += 32) s += qp[d] * kp[d];
        #pragma unroll
        for (int o = 16; o; o >>= 1) s += __shfl_xor_sync(0xffffffffu, s, o);
        if (lane == 0) sc[w] = s * (1.0f / 16.0f);
    }
    __syncthreads();
    float e[KE], m = -1e30f;
    #pragma unroll
    for (int k = 0; k < KE; k++) m = fmaxf(m, sc[k]);
    float sum = 0.f;
    #pragma unroll
    for (int k = 0; k < KE; k++) { e[k] = expf(sc[k] - m); sum += e[k]; }
    float inv = 1.f / sum;
    float acc = 0.f;
    const float* vb = vmat + (long)b * KE * Hd + n * HDim + tid;
    #pragma unroll
    for (int k = 0; k < KE; k++) acc += e[k] * inv * vb[(long)k * Hd];
    ctx[(long)b * Hd + n * HDim + tid]   = acc;
    ctx_r[(long)b * Hd + n * HDim + tid] = __float2half_rn(acc);
}

// ---------------- residual add + LayerNorm -----------------------------------
__global__ void add_ln_kernel(const float* __restrict__ a, const float* __restrict__ bvec,
                              const float* __restrict__ g, const float* __restrict__ be,
                              float* __restrict__ out)
{
    const int b = blockIdx.x;
    const long base = (long)b * Hd;
    float vals[4]; float s = 0.f, ss = 0.f;
    #pragma unroll
    for (int t = 0; t < 4; t++) {
        int h = threadIdx.x + t * 256;
        float v = a[base + h] + bvec[base + h];
        vals[t] = v; s += v; ss += v * v;
    }
    __shared__ float red[16];
    #pragma unroll
    for (int o = 16; o; o >>= 1) {
        s  += __shfl_xor_sync(0xffffffffu, s, o);
        ss += __shfl_xor_sync(0xffffffffu, ss, o);
    }
    int w = threadIdx.x >> 5;
    if ((threadIdx.x & 31) == 0) { red[w] = s; red[8 + w] = ss; }
    __syncthreads();
    s = 0.f; ss = 0.f;
    #pragma unroll
    for (int i = 0; i < 8; i++) { s += red[i]; ss += red[8 + i]; }
    float mean = s * (1.f / Hd);
    float rstd = rsqrtf(ss * (1.f / Hd) - mean * mean + EPSv);
    #pragma unroll
    for (int t = 0; t < 4; t++) {
        int h = threadIdx.x + t * 256;
        out[base + h] = (vals[t] - mean) * rstd * g[h] + be[h];
    }
}

// ---------------- gate logits + softmax + expert mix -------------------------
__global__ void gate_mix_kernel(const float* __restrict__ context, const float* __restrict__ W_gate,
                                const float* __restrict__ b_gate, const float* __restrict__ h_new,
                                float* __restrict__ logits_out, float* __restrict__ gt_out,
                                float* __restrict__ mixed, __half* __restrict__ mixed_r)
{
    const int b = blockIdx.x;
    const int tid = threadIdx.x, lane = tid & 31, w = tid >> 5;
    __shared__ float sl[KE];
    const float* cr = context + (long)b * Hd;
    {
        const float* wg = W_gate + (long)w * Hd;
        float s = 0.f;
        for (int h = lane; h < Hd; h += 32) s += cr[h] * wg[h];
        #pragma unroll
        for (int o = 16; o; o >>= 1) s += __shfl_xor_sync(0xffffffffu, s, o);
        if (lane == 0) sl[w] = s + b_gate[w];
    }
    __syncthreads();
    float lg[KE], m = -1e30f;
    #pragma unroll
    for (int k = 0; k < KE; k++) { lg[k] = sl[k]; m = fmaxf(m, lg[k]); }
    float e[KE], sum = 0.f;
    #pragma unroll
    for (int k = 0; k < KE; k++) { e[k] = expf(lg[k] - m); sum += e[k]; }
    float inv = 1.f / sum;
    if (tid < KE) {
        logits_out[(long)b * KE + tid] = lg[tid];
        gt_out[(long)b * KE + tid]     = e[tid] * inv;
    }
    const float* hb = h_new + (long)b * KE * Hd;
    #pragma unroll
    for (int t = 0; t < 4; t++) {
        int h = tid + t * 256;
        float acc = 0.f;
        #pragma unroll
        for (int k = 0; k < KE; k++) acc += e[k] * inv * hb[(long)k * Hd + h];
        mixed[(long)b * Hd + h]   = acc;
        mixed_r[(long)b * Hd + h] = __float2half_rn(acc);
    }
}

// ---------------- host orchestration -----------------------------------------
static void launch_round(const float* in, __half* out, long n)
{
    int n8 = (int)(n / 8);
    round_f16_kernel<<<(n8 + 255) / 256, 256>>>((const float4*)in, (uint4*)out, n8);
}

static void launch_mma(const __half* A, const __half* Bm, const float* bias, float* C,
                       __half* Cr, int M, int N, int Kd, int lda, int ldb, int ldc,
                       int batch, long aBat, long bBat, long cBat, long biasBat)
{
    dim3 grid(N / 128, M / 128, batch);
    mma_tn<<<grid, 256, SMEMB>>>(A, Bm, bias, C, Cr, Kd, lda, ldb, ldc,
                                 aBat, bBat, cBat, biasBat);
}

extern "C" void kernel_launch(void* const* d_in, const int* in_sizes, int n_in,
                              void* d_out, int out_size)
{
    const float* x_t     = (const float*)d_in[0];
    const float* h_prev  = (const float*)d_in[1];
    const float* W_ih    = (const float*)d_in[2];
    const float* W_hh    = (const float*)d_in[3];
    const float* b_ih    = (const float*)d_in[4];
    const float* b_hh    = (const float*)d_in[5];
    const float* ln_g    = (const float*)d_in[6];
    const float* ln_b    = (const float*)d_in[7];
    const float* Wq_proj = (const float*)d_in[8];
    const float* bq_proj = (const float*)d_in[9];
    const float* W_q     = (const float*)d_in[10];
    const float* W_k     = (const float*)d_in[11];
    const float* W_v     = (const float*)d_in[12];
    const float* b_q     = (const float*)d_in[13];
    const float* b_k     = (const float*)d_in[14];
    const float* b_v     = (const float*)d_in[15];
    const float* W_o     = (const float*)d_in[16];
    const float* b_o     = (const float*)d_in[17];
    const float* aln_g   = (const float*)d_in[18];
    const float* aln_b   = (const float*)d_in[19];
    const float* W_gate  = (const float*)d_in[20];
    const float* b_gate  = (const float*)d_in[21];
    const float* W_read  = (const float*)d_in[22];
    const float* b_read  = (const float*)d_in[23];

    float* out    = (float*)d_out;
    float* h_new  = out;                                   // (B,K,H)
    float* y_hat  = out + (long)Bsz * KE * Hd;             // (B,O)
    float* g_t    = y_hat + (long)Bsz * Oo;                // (B,K)
    float* logits = g_t + (long)Bsz * KE;                  // (B,K)

    float *gi, *gh, *query, *qm, *kmat, *vmat, *ctx, *attnout, *contextb, *mixed;
    __half *xr, *hpr, *Wihr, *Whhr, *Wqpr, *Wqr, *Wkr, *Wvr, *Wor, *Wrdr;
    __half *queryr, *hnewr, *ctxr, *mixedr;
    cudaGetSymbolAddress((void**)&gi, g_gi);
    cudaGetSymbolAddress((void**)&gh, g_gh);
    cudaGetSymbolAddress((void**)&query, g_query);
    cudaGetSymbolAddress((void**)&qm, g_q);
    cudaGetSymbolAddress((void**)&kmat, g_kmat);
    cudaGetSymbolAddress((void**)&vmat, g_vmat);
    cudaGetSymbolAddress((void**)&ctx, g_ctx);
    cudaGetSymbolAddress((void**)&attnout, g_attnout);
    cudaGetSymbolAddress((void**)&contextb, g_context);
    cudaGetSymbolAddress((void**)&mixed, g_mixed);
    cudaGetSymbolAddress((void**)&xr, g_xr);
    cudaGetSymbolAddress((void**)&hpr, g_hpr);
    cudaGetSymbolAddress((void**)&Wihr, g_Wihr);
    cudaGetSymbolAddress((void**)&Whhr, g_Whhr);
    cudaGetSymbolAddress((void**)&Wqpr, g_Wqpr);
    cudaGetSymbolAddress((void**)&Wqr, g_Wqr);
    cudaGetSymbolAddress((void**)&Wkr, g_Wkr);
    cudaGetSymbolAddress((void**)&Wvr, g_Wvr);
    cudaGetSymbolAddress((void**)&Wor, g_Wor);
    cudaGetSymbolAddress((void**)&Wrdr, g_Wrdr);
    cudaGetSymbolAddress((void**)&queryr, g_queryr);
    cudaGetSymbolAddress((void**)&hnewr, g_hnewr);
    cudaGetSymbolAddress((void**)&ctxr, g_ctxr);
    cudaGetSymbolAddress((void**)&mixedr, g_mixedr);

    cudaFuncSetAttribute(mma_tn, cudaFuncAttributeMaxDynamicSharedMemorySize, SMEMB);

    // 0) pre-round all harness-provided GEMM operands to fp16
    launch_round(x_t,     xr,   (long)Bsz * Din);
    launch_round(h_prev,  hpr,  (long)Bsz * KE * Hd);
    launch_round(W_ih,    Wihr, (long)KE * 3 * Hd * Din);
    launch_round(W_hh,    Whhr, (long)KE * 3 * Hd * Hd);
    launch_round(Wq_proj, Wqpr, (long)Hd * Din);
    launch_round(W_q,     Wqr,  (long)Hd * Hd);
    launch_round(W_k,     Wkr,  (long)Hd * Hd);
    launch_round(W_v,     Wvr,  (long)Hd * Hd);
    launch_round(W_o,     Wor,  (long)Hd * Hd);
    launch_round(W_read,  Wrdr, (long)Oo * Hd);

    // 1) gi = x_t @ W_ih^T + b_ih          (4096 x 24576 x 512)
    launch_mma(xr, Wihr, b_ih, gi, nullptr, Bsz, KE * 3 * Hd, Din,
               Din, Din, KE * 3 * Hd, 1, 0, 0, 0, 0);
    // 2) gh[k] = h_prev[:,k,:] @ W_hh[k]^T + b_hh[k]   (batched over K)
    launch_mma(hpr, Whhr, b_hh, gh, nullptr, Bsz, 3 * Hd, Hd,
               KE * Hd, Hd, KE * 3 * Hd, KE,
               (long)Hd, (long)3 * Hd * Hd, (long)3 * Hd, (long)3 * Hd);
    // 3) GRU pointwise + per-expert LN -> h_new (d_out) + fp16 copy
    gru_ln_kernel<<<Bsz * KE, 256>>>(gi, gh, h_prev, ln_g, ln_b, h_new, hnewr);
    // 4) query = x_t @ Wq_proj^T + bq_proj   (+ fp16 copy for step 5)
    launch_mma(xr, Wqpr, bq_proj, query, queryr, Bsz, Hd, Din,
               Din, Din, Hd, 1, 0, 0, 0, 0);
    // 5) q = query @ W_q^T + b_q
    launch_mma(queryr, Wqr, b_q, qm, nullptr, Bsz, Hd, Hd, Hd, Hd, Hd, 1, 0, 0, 0, 0);
    // 6) kmat = h_new @ W_k^T + b_k     (32768 x 1024 x 1024)
    launch_mma(hnewr, Wkr, b_k, kmat, nullptr, Bsz * KE, Hd, Hd, Hd, Hd, Hd, 1, 0, 0, 0, 0);
    // 7) vmat = h_new @ W_v^T + b_v
    launch_mma(hnewr, Wvr, b_v, vmat, nullptr, Bsz * KE, Hd, Hd, Hd, Hd, Hd, 1, 0, 0, 0, 0);
    // 8) attention -> ctx (+ fp16 copy)
    attn_kernel<<<Bsz * NHh, 256>>>(qm, kmat, vmat, ctx, ctxr);
    // 9) attn_out = ctx @ W_o^T + b_o
    launch_mma(ctxr, Wor, b_o, attnout, nullptr, Bsz, Hd, Hd, Hd, Hd, Hd, 1, 0, 0, 0, 0);
    // 10) context = LN(query + attn_out)
    add_ln_kernel<<<Bsz, 256>>>(query, attnout, aln_g, aln_b, contextb);
    // 11) gate logits + softmax + mix (+ fp16 mixed)
    gate_mix_kernel<<<Bsz, 256>>>(contextb, W_gate, b_gate, h_new, logits, g_t, mixed, mixedr);
    // 12) y_hat = mixed @ W_read^T + b_read
    launch_mma(mixedr, Wrdr, b_read, y_hat, nullptr, Bsz, Oo, Hd, Hd, Hd, Oo, 1, 0, 0, 0, 0);
}

// round 16
// speedup vs baseline: 2.5325x; 1.0550x over previous
#include <cuda_runtime.h>
#include <cuda_fp16.h>
#include <math.h>
#include <stdint.h>

#define Bsz  4096
#define Din  512
#define Hd   1024
#define KE   8
#define Oo   256
#define NHh  4
#define HDim 256
#define EPSv 1e-5f

// ---------------- scratch (device globals; no allocations allowed) ----------
__device__ float g_gi[(size_t)Bsz * KE * 3 * Hd];   // (B, K, 3H)
__device__ float g_gh[(size_t)Bsz * KE * 3 * Hd];   // (B, K, 3H)
__device__ float g_query[(size_t)Bsz * Hd];
__device__ float g_q[(size_t)Bsz * Hd];
__device__ float g_kmat[(size_t)Bsz * KE * Hd];
__device__ float g_vmat[(size_t)Bsz * KE * Hd];
__device__ float g_ctx[(size_t)Bsz * Hd];
__device__ float g_attnout[(size_t)Bsz * Hd];
__device__ float g_context[(size_t)Bsz * Hd];
__device__ float g_mixed[(size_t)Bsz * Hd];

// fp16 operand copies (GEMM inputs)
__device__ __half g_xr[(size_t)Bsz * Din];
__device__ __half g_hpr[(size_t)Bsz * KE * Hd];
__device__ __half g_Wihr[(size_t)KE * 3 * Hd * Din];
__device__ __half g_Whhr[(size_t)KE * 3 * Hd * Hd];
__device__ __half g_Wqpr[(size_t)Hd * Din];
__device__ __half g_Wqr[(size_t)Hd * Hd];
__device__ __half g_Wkr[(size_t)Hd * Hd];
__device__ __half g_Wvr[(size_t)Hd * Hd];
__device__ __half g_Wor[(size_t)Hd * Hd];
__device__ __half g_Wrdr[(size_t)Oo * Hd];
__device__ __half g_queryr[(size_t)Bsz * Hd];
__device__ __half g_hnewr[(size_t)Bsz * KE * Hd];
__device__ __half g_ctxr[(size_t)Bsz * Hd];
__device__ __half g_mixedr[(size_t)Bsz * Hd];

// ---------------- helpers ----------------------------------------------------
__device__ __forceinline__ void mma16n8k16(float* c, const uint32_t* a, const uint32_t* b) {
    asm volatile("mma.sync.aligned.m16n8k16.row.col.f32.f16.f16.f32 "
        "{%0,%1,%2,%3}, {%4,%5,%6,%7}, {%8,%9}, {%0,%1,%2,%3};"
        : "+f"(c[0]), "+f"(c[1]), "+f"(c[2]), "+f"(c[3])
        : "r"(a[0]), "r"(a[1]), "r"(a[2]), "r"(a[3]), "r"(b[0]), "r"(b[1]));
}
#define LDSM_X4(r0, r1, r2, r3, addr)                                          \
    asm volatile("ldmatrix.sync.aligned.m8n8.x4.shared.b16 {%0,%1,%2,%3}, [%4];" \
        : "=r"(r0), "=r"(r1), "=r"(r2), "=r"(r3) : "r"(addr))
__device__ __forceinline__ uint32_t smem_u32(const void* p) {
    uint32_t a;
    asm("{ .reg .u64 t; cvta.to.shared.u64 t, %1; cvt.u32.u64 %0, t; }" : "=r"(a) : "l"(p));
    return a;
}
__device__ __forceinline__ void cp_async16(uint32_t dst, const void* src) {
    asm volatile("cp.async.cg.shared.global [%0], [%1], 16;" :: "r"(dst), "l"(src));
}
#define CP_COMMIT()  asm volatile("cp.async.commit_group;" ::: "memory")
#define CP_WAIT(n)   asm volatile("cp.async.wait_group %0;" :: "n"(n) : "memory")

// ---------------- elementwise fp32 -> fp16 rounding --------------------------
__global__ void round_f16_kernel(const float4* __restrict__ in, uint4* __restrict__ out, int n8)
{
    int i = blockIdx.x * 256 + threadIdx.x;
    if (i < n8) {
        float4 a = in[2 * i], b = in[2 * i + 1];
        union { uint4 u; __half2 h[4]; } o;
        o.h[0] = __floats2half2_rn(a.x, a.y);
        o.h[1] = __floats2half2_rn(a.z, a.w);
        o.h[2] = __floats2half2_rn(b.x, b.y);
        o.h[3] = __floats2half2_rn(b.z, b.w);
        out[i] = o.u;
    }
}

// ================= fp16 mma.sync TN GEMM (ldmatrix mainloop) =================
// C[m,n] = sum_k A[m,k]*B[n,k] + bias[n]; A,B fp16, accumulate fp32.
// Block 128x128, K-chunk 32, 256 threads (8 warps: 2M x 4N, warp tile 64x32).
// Smem stage: row stride 40 halves -> ldmatrix 8-row phases hit word-banks
// {0,20,8,28,16,4,24,12}: all 32 banks exactly once, conflict-free.
// 3-stage cp.async, ONE barrier per chunk (wait -> sync -> issue -> compute);
// uniform group-count invariant (empty commit in tail) so wait_group(1)
// provably retires chunk c's group, including the last chunk.
#define ROW_H   40                          // halves per smem row (32 data + 8 pad)
#define A_STG_H (128 * ROW_H)               // halves per matrix-stage
#define STAGE_H (2 * A_STG_H)               // A + B per stage
#define NSTAGE  3
#define SMEMB   (NSTAGE * STAGE_H * 2)      // 61440 bytes

__global__ __launch_bounds__(256, 2)
void mma_tn(const __half* __restrict__ A, const __half* __restrict__ Bm,
            const float* __restrict__ bias, float* __restrict__ C,
            __half* __restrict__ Cr,         // optional fp16-rounded copy of C
            int Kd, int lda, int ldb, int ldc,
            long aBat, long bBat, long cBat, long biasBat)
{
    extern __shared__ __half smh[];
    const int tid  = threadIdx.x;
    const int wid  = tid >> 5;
    const int lane = tid & 31;
    const int warpM = wid & 1;        // 0..1  (64 rows each)
    const int warpN = wid >> 1;       // 0..3  (32 cols each)
    const int r = lane >> 2;          // 0..7
    const int q = lane & 3;           // 0..3

    const int bz = blockIdx.z;
    A  += (long)bz * aBat;
    Bm += (long)bz * bBat;
    C  += (long)bz * cBat;
    const float* biasp = bias ? bias + (long)bz * biasBat : nullptr;

    const int rowBase = blockIdx.y * 128;
    const int colBase = blockIdx.x * 128;

    const int lrow = tid >> 2;        // 0..63 -> covers 128 rows via i*64
    const int lk8  = (tid & 3) * 8;   // 0,8,16,24 (halves)

    const uint32_t smb = smem_u32(smh);

    // ldmatrix lane-address components (see header comment for mapping proof)
    const int aRow  = lane & 15;                         // fragment row
    const int aKoff = (lane >> 4) << 3;                  // 0 | 8 halves
    const int bRow  = (lane & 7) + ((lane >> 4) << 3);   // n-row within 16
    const int bKoff = ((lane >> 3) & 1) << 3;            // 0 | 8 halves

    // issue cp.async for one 32-wide K chunk into stage s (one group)
    auto issue_chunk = [&](int k0, int s) {
        const uint32_t abase = smb + s * (STAGE_H * 2);
        const uint32_t bbase = abase + A_STG_H * 2;
        #pragma unroll
        for (int i = 0; i < 2; i++) {
            int row = lrow + i * 64;
            cp_async16(abase + (row * ROW_H + lk8) * 2,
                       A + (long)(rowBase + row) * lda + k0 + lk8);
            cp_async16(bbase + (row * ROW_H + lk8) * 2,
                       Bm + (long)(colBase + row) * ldb + k0 + lk8);
        }
        CP_COMMIT();
    };

    float acc[4][4][4];
    #pragma unroll
    for (int mt = 0; mt < 4; mt++)
        #pragma unroll
        for (int nt = 0; nt < 4; nt++)
            #pragma unroll
            for (int j = 0; j < 4; j++) acc[mt][nt][j] = 0.0f;

    const int NC = Kd >> 5;

    // prologue: prefetch chunks 0 and 1 -> groups G0, G1
    issue_chunk(0, 0);
    if (NC > 1) issue_chunk(32, 1);
    else        CP_COMMIT();          // keep group-count invariant for NC==1

    for (int c = 0; c < NC; c++) {
        const int s = c % NSTAGE;
        CP_WAIT(1);                   // newest group is G(c+1) -> G(c) retired
        __syncthreads();              // stage c ready; stage (c-1) fully read

        // prefetch into stage (c+2)%3 == (c-1)%3 (or EMPTY group in tail)
        if (c + 2 < NC) issue_chunk((c + 2) * 32, (c + 2) % NSTAGE);
        else            CP_COMMIT();

        const uint32_t aBase = smb + 2 * (s * STAGE_H
                             + (warpM * 64 + aRow) * ROW_H + aKoff);
        const uint32_t bBase = smb + 2 * (s * STAGE_H + A_STG_H
                             + (warpN * 32 + bRow) * ROW_H + bKoff);

        #pragma unroll
        for (int ks = 0; ks < 2; ks++) {
            const int k0h = ks * 16;
            uint32_t afr[4][4], bfr[4][2];
            #pragma unroll
            for (int mt = 0; mt < 4; mt++)
                LDSM_X4(afr[mt][0], afr[mt][1], afr[mt][2], afr[mt][3],
                        aBase + 2 * (mt * 16 * ROW_H + k0h));
            #pragma unroll
            for (int np = 0; np < 2; np++)
                LDSM_X4(bfr[2 * np][0], bfr[2 * np][1],
                        bfr[2 * np + 1][0], bfr[2 * np + 1][1],
                        bBase + 2 * (np * 16 * ROW_H + k0h));
            #pragma unroll
            for (int mt = 0; mt < 4; mt++)
                #pragma unroll
                for (int nt = 0; nt < 4; nt++)
                    mma16n8k16(acc[mt][nt], afr[mt], bfr[nt]);
        }
    }

    // ---- epilogue: acc -> C (+bias), optional fp16 copy ----
    #pragma unroll
    for (int mt = 0; mt < 4; mt++) {
        const int row = rowBase + warpM * 64 + mt * 16 + r;
        #pragma unroll
        for (int nt = 0; nt < 4; nt++) {
            const int col = colBase + warpN * 32 + nt * 8 + q * 2;
            float b0 = 0.f, b1 = 0.f;
            if (biasp) { b0 = biasp[col]; b1 = biasp[col + 1]; }
            float2 v0, v1;
            v0.x = acc[mt][nt][0] + b0; v0.y = acc[mt][nt][1] + b1;
            v1.x = acc[mt][nt][2] + b0; v1.y = acc[mt][nt][3] + b1;
            *(float2*)(C + (long)row * ldc + col)       = v0;
            *(float2*)(C + (long)(row + 8) * ldc + col) = v1;
            if (Cr) {
                *(__half2*)(Cr + (long)row * ldc + col)       = __floats2half2_rn(v0.x, v0.y);
                *(__half2*)(Cr + (long)(row + 8) * ldc + col) = __floats2half2_rn(v1.x, v1.y);
            }
        }
    }
}

// ---------------- GRU pointwise + per-expert LayerNorm -----------------------
__global__ void gru_ln_kernel(const float* __restrict__ gi, const float* __restrict__ gh,
                              const float* __restrict__ h_prev,
                              const float* __restrict__ ln_g, const float* __restrict__ ln_b,
                              float* __restrict__ h_new, __half* __restrict__ h_new_r)
{
    const int bk = blockIdx.x;
    const int k  = bk & (KE - 1);
    const long giBase = (long)bk * (3 * Hd);
    const long hBase  = (long)bk * Hd;
    const float* gir = gi + giBase;
    const float* ghr = gh + giBase;
    const float* hp  = h_prev + hBase;

    float vals[4];
    float s = 0.f, ss = 0.f;
    #pragma unroll
    for (int t = 0; t < 4; t++) {
        int h = threadIdx.x + t * 256;
        float ir = gir[h],           hr = ghr[h];
        float iz = gir[Hd + h],      hz = ghr[Hd + h];
        float inn = gir[2 * Hd + h], hn = ghr[2 * Hd + h];
        float r = 1.f / (1.f + expf(-(ir + hr)));
        float z = 1.f / (1.f + expf(-(iz + hz)));
        float n = tanhf(inn + r * hn);
        float hv = (1.f - z) * n + z * hp[h];
        vals[t] = hv; s += hv; ss += hv * hv;
    }
    __shared__ float red[16];
    #pragma unroll
    for (int o = 16; o; o >>= 1) {
        s  += __shfl_xor_sync(0xffffffffu, s, o);
        ss += __shfl_xor_sync(0xffffffffu, ss, o);
    }
    int w = threadIdx.x >> 5;
    if ((threadIdx.x & 31) == 0) { red[w] = s; red[8 + w] = ss; }
    __syncthreads();
    s = 0.f; ss = 0.f;
    #pragma unroll
    for (int i = 0; i < 8; i++) { s += red[i]; ss += red[8 + i]; }
    float mean = s * (1.f / Hd);
    float var  = ss * (1.f / Hd) - mean * mean;
    float rstd = rsqrtf(var + EPSv);
    #pragma unroll
    for (int t = 0; t < 4; t++) {
        int h = threadIdx.x + t * 256;
        float o = (vals[t] - mean) * rstd * ln_g[k * Hd + h] + ln_b[k * Hd + h];
        h_new[hBase + h]   = o;
        h_new_r[hBase + h] = __float2half_rn(o);
    }
}

// ---------------- attention over K=8 expert states ---------------------------
__global__ void attn_kernel(const float* __restrict__ q, const float* __restrict__ kmat,
                            const float* __restrict__ vmat, float* __restrict__ ctx,
                            __half* __restrict__ ctx_r)
{
    const int b = blockIdx.x >> 2;
    const int n = blockIdx.x & 3;
    const int tid = threadIdx.x;
    const int lane = tid & 31, w = tid >> 5;
    __shared__ float sc[KE];
    const float* qp = q + (long)b * Hd + n * HDim;
    {
        const float* kp = kmat + (long)b * KE * Hd + (long)w * Hd + n * HDim;
        float s = 0.f;
        #pragma unroll
        for (int d = lane; d < HDim; d += 32) s += qp[d] * kp[d];
        #pragma unroll
        for (int o = 16; o; o >>= 1) s += __shfl_xor_sync(0xffffffffu, s, o);
        if (lane == 0) sc[w] = s * (1.0f / 16.0f);
    }
    __syncthreads();
    float e[KE], m = -1e30f;
    #pragma unroll
    for (int k = 0; k < KE; k++) m = fmaxf(m, sc[k]);
    float sum = 0.f;
    #pragma unroll
    for (int k = 0; k < KE; k++) { e[k] = expf(sc[k] - m); sum += e[k]; }
    float inv = 1.f / sum;
    float acc = 0.f;
    const float* vb = vmat + (long)b * KE * Hd + n * HDim + tid;
    #pragma unroll
    for (int k = 0; k < KE; k++) acc += e[k] * inv * vb[(long)k * Hd];
    ctx[(long)b * Hd + n * HDim + tid]   = acc;
    ctx_r[(long)b * Hd + n * HDim + tid] = __float2half_rn(acc);
}

// ---------------- residual add + LayerNorm -----------------------------------
__global__ void add_ln_kernel(const float* __restrict__ a, const float* __restrict__ bvec,
                              const float* __restrict__ g, const float* __restrict__ be,
                              float* __restrict__ out)
{
    const int b = blockIdx.x;
    const long base = (long)b * Hd;
    float vals[4]; float s = 0.f, ss = 0.f;
    #pragma unroll
    for (int t = 0; t < 4; t++) {
        int h = threadIdx.x + t * 256;
        float v = a[base + h] + bvec[base + h];
        vals[t] = v; s += v; ss += v * v;
    }
    __shared__ float red[16];
    #pragma unroll
    for (int o = 16; o; o >>= 1) {
        s  += __shfl_xor_sync(0xffffffffu, s, o);
        ss += __shfl_xor_sync(0xffffffffu, ss, o);
    }
    int w = threadIdx.x >> 5;
    if ((threadIdx.x & 31) == 0) { red[w] = s; red[8 + w] = ss; }
    __syncthreads();
    s = 0.f; ss = 0.f;
    #pragma unroll
    for (int i = 0; i < 8; i++) { s += red[i]; ss += red[8 + i]; }
    float mean = s * (1.f / Hd);
    float rstd = rsqrtf(ss * (1.f / Hd) - mean * mean + EPSv);
    #pragma unroll
    for (int t = 0; t < 4; t++) {
        int h = threadIdx.x + t * 256;
        out[base + h] = (vals[t] - mean) * rstd * g[h] + be[h];
    }
}

// ---------------- gate logits + softmax + expert mix -------------------------
__global__ void gate_mix_kernel(const float* __restrict__ context, const float* __restrict__ W_gate,
                                const float* __restrict__ b_gate, const float* __restrict__ h_new,
                                float* __restrict__ logits_out, float* __restrict__ gt_out,
                                float* __restrict__ mixed, __half* __restrict__ mixed_r)
{
    const int b = blockIdx.x;
    const int tid = threadIdx.x, lane = tid & 31, w = tid >> 5;
    __shared__ float sl[KE];
    const float* cr = context + (long)b * Hd;
    {
        const float* wg = W_gate + (long)w * Hd;
        float s = 0.f;
        for (int h = lane; h < Hd; h += 32) s += cr[h] * wg[h];
        #pragma unroll
        for (int o = 16; o; o >>= 1) s += __shfl_xor_sync(0xffffffffu, s, o);
        if (lane == 0) sl[w] = s + b_gate[w];
    }
    __syncthreads();
    float lg[KE], m = -1e30f;
    #pragma unroll
    for (int k = 0; k < KE; k++) { lg[k] = sl[k]; m = fmaxf(m, lg[k]); }
    float e[KE], sum = 0.f;
    #pragma unroll
    for (int k = 0; k < KE; k++) { e[k] = expf(lg[k] - m); sum += e[k]; }
    float inv = 1.f / sum;
    if (tid < KE) {
        logits_out[(long)b * KE + tid] = lg[tid];
        gt_out[(long)b * KE + tid]     = e[tid] * inv;
    }
    const float* hb = h_new + (long)b * KE * Hd;
    #pragma unroll
    for (int t = 0; t < 4; t++) {
        int h = tid + t * 256;
        float acc = 0.f;
        #pragma unroll
        for (int k = 0; k < KE; k++) acc += e[k] * inv * hb[(long)k * Hd + h];
        mixed[(long)b * Hd + h]   = acc;
        mixed_r[(long)b * Hd + h] = __float2half_rn(acc);
    }
}

// ---------------- host orchestration -----------------------------------------
static void launch_round(const float* in, __half* out, long n)
{
    int n8 = (int)(n / 8);
    round_f16_kernel<<<(n8 + 255) / 256, 256>>>((const float4*)in, (uint4*)out, n8);
}

static void launch_mma(const __half* A, const __half* Bm, const float* bias, float* C,
                       __half* Cr, int M, int N, int Kd, int lda, int ldb, int ldc,
                       int batch, long aBat, long bBat, long cBat, long biasBat)
{
    dim3 grid(N / 128, M / 128, batch);
    mma_tn<<<grid, 256, SMEMB>>>(A, Bm, bias, C, Cr, Kd, lda, ldb, ldc,
                                 aBat, bBat, cBat, biasBat);
}

extern "C" void kernel_launch(void* const* d_in, const int* in_sizes, int n_in,
                              void* d_out, int out_size)
{
    const float* x_t     = (const float*)d_in[0];
    const float* h_prev  = (const float*)d_in[1];
    const float* W_ih    = (const float*)d_in[2];
    const float* W_hh    = (const float*)d_in[3];
    const float* b_ih    = (const float*)d_in[4];
    const float* b_hh    = (const float*)d_in[5];
    const float* ln_g    = (const float*)d_in[6];
    const float* ln_b    = (const float*)d_in[7];
    const float* Wq_proj = (const float*)d_in[8];
    const float* bq_proj = (const float*)d_in[9];
    const float* W_q     = (const float*)d_in[10];
    const float* W_k     = (const float*)d_in[11];
    const float* W_v     = (const float*)d_in[12];
    const float* b_q     = (const float*)d_in[13];
    const float* b_k     = (const float*)d_in[14];
    const float* b_v     = (const float*)d_in[15];
    const float* W_o     = (const float*)d_in[16];
    const float* b_o     = (const float*)d_in[17];
    const float* aln_g   = (const float*)d_in[18];
    const float* aln_b   = (const float*)d_in[19];
    const float* W_gate  = (const float*)d_in[20];
    const float* b_gate  = (const float*)d_in[21];
    const float* W_read  = (const float*)d_in[22];
    const float* b_read  = (const float*)d_in[23];

    float* out    = (float*)d_out;
    float* h_new  = out;                                   // (B,K,H)
    float* y_hat  = out + (long)Bsz * KE * Hd;             // (B,O)
    float* g_t    = y_hat + (long)Bsz * Oo;                // (B,K)
    float* logits = g_t + (long)Bsz * KE;                  // (B,K)

    float *gi, *gh, *query, *qm, *kmat, *vmat, *ctx, *attnout, *contextb, *mixed;
    __half *xr, *hpr, *Wihr, *Whhr, *Wqpr, *Wqr, *Wkr, *Wvr, *Wor, *Wrdr;
    __half *queryr, *hnewr, *ctxr, *mixedr;
    cudaGetSymbolAddress((void**)&gi, g_gi);
    cudaGetSymbolAddress((void**)&gh, g_gh);
    cudaGetSymbolAddress((void**)&query, g_query);
    cudaGetSymbolAddress((void**)&qm, g_q);
    cudaGetSymbolAddress((void**)&kmat, g_kmat);
    cudaGetSymbolAddress((void**)&vmat, g_vmat);
    cudaGetSymbolAddress((void**)&ctx, g_ctx);
    cudaGetSymbolAddress((void**)&attnout, g_attnout);
    cudaGetSymbolAddress((void**)&contextb, g_context);
    cudaGetSymbolAddress((void**)&mixed, g_mixed);
    cudaGetSymbolAddress((void**)&xr, g_xr);
    cudaGetSymbolAddress((void**)&hpr, g_hpr);
    cudaGetSymbolAddress((void**)&Wihr, g_Wihr);
    cudaGetSymbolAddress((void**)&Whhr, g_Whhr);
    cudaGetSymbolAddress((void**)&Wqpr, g_Wqpr);
    cudaGetSymbolAddress((void**)&Wqr, g_Wqr);
    cudaGetSymbolAddress((void**)&Wkr, g_Wkr);
    cudaGetSymbolAddress((void**)&Wvr, g_Wvr);
    cudaGetSymbolAddress((void**)&Wor, g_Wor);
    cudaGetSymbolAddress((void**)&Wrdr, g_Wrdr);
    cudaGetSymbolAddress((void**)&queryr, g_queryr);
    cudaGetSymbolAddress((void**)&hnewr, g_hnewr);
    cudaGetSymbolAddress((void**)&ctxr, g_ctxr);
    cudaGetSymbolAddress((void**)&mixedr, g_mixedr);

    cudaFuncSetAttribute(mma_tn, cudaFuncAttributeMaxDynamicSharedMemorySize, SMEMB);

    // 0) pre-round all harness-provided GEMM operands to fp16
    launch_round(x_t,     xr,   (long)Bsz * Din);
    launch_round(h_prev,  hpr,  (long)Bsz * KE * Hd);
    launch_round(W_ih,    Wihr, (long)KE * 3 * Hd * Din);
    launch_round(W_hh,    Whhr, (long)KE * 3 * Hd * Hd);
    launch_round(Wq_proj, Wqpr, (long)Hd * Din);
    launch_round(W_q,     Wqr,  (long)Hd * Hd);
    launch_round(W_k,     Wkr,  (long)Hd * Hd);
    launch_round(W_v,     Wvr,  (long)Hd * Hd);
    launch_round(W_o,     Wor,  (long)Hd * Hd);
    launch_round(W_read,  Wrdr, (long)Oo * Hd);

    // 1) gi = x_t @ W_ih^T + b_ih          (4096 x 24576 x 512)
    launch_mma(xr, Wihr, b_ih, gi, nullptr, Bsz, KE * 3 * Hd, Din,
               Din, Din, KE * 3 * Hd, 1, 0, 0, 0, 0);
    // 2) gh[k] = h_prev[:,k,:] @ W_hh[k]^T + b_hh[k]   (batched over K)
    launch_mma(hpr, Whhr, b_hh, gh, nullptr, Bsz, 3 * Hd, Hd,
               KE * Hd, Hd, KE * 3 * Hd, KE,
               (long)Hd, (long)3 * Hd * Hd, (long)3 * Hd, (long)3 * Hd);
    // 3) GRU pointwise + per-expert LN -> h_new (d_out) + fp16 copy
    gru_ln_kernel<<<Bsz * KE, 256>>>(gi, gh, h_prev, ln_g, ln_b, h_new, hnewr);
    // 4) query = x_t @ Wq_proj^T + bq_proj   (+ fp16 copy for step 5)
    launch_mma(xr, Wqpr, bq_proj, query, queryr, Bsz, Hd, Din,
               Din, Din, Hd, 1, 0, 0, 0, 0);
    // 5) q = query @ W_q^T + b_q
    launch_mma(queryr, Wqr, b_q, qm, nullptr, Bsz, Hd, Hd, Hd, Hd, Hd, 1, 0, 0, 0, 0);
    // 6) kmat = h_new @ W_k^T + b_k     (32768 x 1024 x 1024)
    launch_mma(hnewr, Wkr, b_k, kmat, nullptr, Bsz * KE, Hd, Hd, Hd, Hd, Hd, 1, 0, 0, 0, 0);
    // 7) vmat = h_new @ W_v^T + b_v
    launch_mma(hnewr, Wvr, b_v, vmat, nullptr, Bsz * KE, Hd, Hd, Hd, Hd, Hd, 1, 0, 0, 0, 0);
    // 8) attention -> ctx (+ fp16 copy)
    attn_kernel<<<Bsz * NHh, 256>>>(qm, kmat, vmat, ctx, ctxr);
    // 9) attn_out = ctx @ W_o^T + b_o
    launch_mma(ctxr, Wor, b_o, attnout, nullptr, Bsz, Hd, Hd, Hd, Hd, Hd, 1, 0, 0, 0, 0);
    // 10) context = LN(query + attn_out)
    add_ln_kernel<<<Bsz, 256>>>(query, attnout, aln_g, aln_b, contextb);
    // 11) gate logits + softmax + mix (+ fp16 mixed)
    gate_mix_kernel<<<Bsz, 256>>>(contextb, W_gate, b_gate, h_new, logits, g_t, mixed, mixedr);
    // 12) y_hat = mixed @ W_read^T + b_read
    launch_mma(mixedr, Wrdr, b_read, y_hat, nullptr, Bsz, Oo, Hd, Hd, Hd, Oo, 1, 0, 0, 0, 0);
}